// round 1
// baseline (speedup 1.0000x reference)
#include <cuda_runtime.h>
#include <cuda_bf16.h>
#include <math.h>

// Problem constants
#define VV 32000
#define EE 512
#define HH 1024
#define BB 32
#define TT 64
#define G4H (4 * HH)          // 4096
#define NROWS (BB * TT)       // 2048

// ---------------- scratch (no allocs allowed) ----------------
__device__ float g_xW[NROWS * G4H];        // [b*T+t, 4H] precomputed input projections (+bias)
__device__ float g_seq[NROWS * HH];        // [b*T+t, H] hidden states per step
__device__ float g_h[2][BB * HH];          // ping-pong hidden state
__device__ float g_c[BB * HH];             // cell state (in-place per-column update is race-free)

// ---------------- init / finalize ----------------
__global__ void init_state_kernel(const float* __restrict__ h0, const float* __restrict__ c0) {
    int i = blockIdx.x * blockDim.x + threadIdx.x;
    if (i < BB * HH) {
        g_h[0][i] = h0[i];
        g_c[i] = c0[i];
    }
}

__global__ void write_state_kernel(float* __restrict__ out_h, float* __restrict__ out_c) {
    int i = blockIdx.x * blockDim.x + threadIdx.x;
    if (i < BB * HH) {
        out_h[i] = g_h[0][i];   // after 64 steps, latest h lives in buffer 0
        out_c[i] = g_c[i];
    }
}

// ---------------- generic fp32 SGEMM ----------------
// C[M,N] = A[M,K] @ B[K,N] + bias[N]
// If GATHER: A row r is A + rowidx[r]*lda (embedding gather), else A + r*lda.
// Requires M%128==0, N%128==0, K%8==0, lda%4==0.
template <bool GATHER>
__global__ __launch_bounds__(256, 2)
void sgemm_kernel(const float* __restrict__ A, const int* __restrict__ rowidx,
                  const float* __restrict__ B, const float* __restrict__ bias,
                  float* __restrict__ C, int M, int N, int K, int lda)
{
    constexpr int BM = 128, BN = 128, BK = 8, TM = 8, TN = 8;
    __shared__ float As[BK][BM];   // transposed A tile
    __shared__ float Bs[BK][BN];

    const int brow = blockIdx.y;
    const int bcol = blockIdx.x;
    const int tid = threadIdx.x;          // 256 threads
    const int tx = tid % 16;              // 16x16 thread grid
    const int ty = tid / 16;

    float acc[TM][TN];
#pragma unroll
    for (int i = 0; i < TM; ++i)
#pragma unroll
        for (int j = 0; j < TN; ++j) acc[i][j] = 0.f;

    // A tile load mapping: 128 rows x 8 k -> 256 float4 (one per thread)
    const int a_r = tid >> 1;             // 0..127
    const int a_k = (tid & 1) * 4;        // 0 or 4
    // B tile load mapping: 8 k x 128 cols -> 256 float4
    const int b_k = tid >> 5;             // 0..7
    const int b_c = (tid & 31) * 4;       // 0..124

    const int grow = brow * BM + a_r;
    const float* Arow;
    if (GATHER) Arow = A + (size_t)rowidx[grow] * lda;
    else        Arow = A + (size_t)grow * lda;

    const float* Bbase = B + (size_t)bcol * BN;

    for (int kt = 0; kt < K; kt += BK) {
        float4 av = *(const float4*)(Arow + kt + a_k);
        As[a_k + 0][a_r] = av.x;
        As[a_k + 1][a_r] = av.y;
        As[a_k + 2][a_r] = av.z;
        As[a_k + 3][a_r] = av.w;
        float4 bv = *(const float4*)(Bbase + (size_t)(kt + b_k) * N + b_c);
        *(float4*)(&Bs[b_k][b_c]) = bv;
        __syncthreads();
#pragma unroll
        for (int k = 0; k < BK; ++k) {
            float ra[TM], rb[TN];
#pragma unroll
            for (int i = 0; i < TM; ++i) ra[i] = As[k][ty * TM + i];
#pragma unroll
            for (int j = 0; j < TN; ++j) rb[j] = Bs[k][tx * TN + j];
#pragma unroll
            for (int i = 0; i < TM; ++i)
#pragma unroll
                for (int j = 0; j < TN; ++j)
                    acc[i][j] += ra[i] * rb[j];
        }
        __syncthreads();
    }

    // epilogue: add bias, vectorized store
    const int ccol0 = bcol * BN + tx * TN;
#pragma unroll
    for (int i = 0; i < TM; ++i) {
        size_t r = (size_t)(brow * BM + ty * TM + i);
        float* crow = C + r * (size_t)N + ccol0;
#pragma unroll
        for (int j = 0; j < TN; j += 4) {
            float4 v;
            v.x = acc[i][j + 0] + bias[ccol0 + j + 0];
            v.y = acc[i][j + 1] + bias[ccol0 + j + 1];
            v.z = acc[i][j + 2] + bias[ccol0 + j + 2];
            v.w = acc[i][j + 3] + bias[ccol0 + j + 3];
            *(float4*)(crow + j) = v;
        }
    }
}

// ---------------- fused LSTM step ----------------
// One launch per timestep t. 128 blocks; block bx owns h-columns [bx*8, bx*8+8)
// and computes z for all 4 gates at those columns across the 32 batch rows,
// then applies gate nonlinearity + state update for its columns.
// Reads h from g_h[t&1], writes new h to g_h[(t+1)&1] (no races), c in-place
// (each c element owned by exactly one block).
__global__ __launch_bounds__(256)
void lstm_step_kernel(const float* __restrict__ U, int t)
{
    const int n0 = blockIdx.x * 8;            // h-column group base
    const int tid = threadIdx.x;              // 256 threads

    const float* __restrict__ hprev = g_h[t & 1];

    __shared__ float hS[32][33];              // [k][m], padded
    __shared__ float uS[32][32];              // [k][local c]  (local c: g*8+j)
    __shared__ float zS[32][33];              // [m][local c], padded

    float acc0 = 0.f, acc1 = 0.f, acc2 = 0.f, acc3 = 0.f;
    const int m = tid & 31;                   // batch row this thread accumulates
    const int cbase = (tid >> 5) * 4;         // 4 local cols per thread

    // load-index mapping (reused every K tile)
    const int lm = tid >> 3;                  // 0..31 : h row to load
    const int kk = (tid & 7) * 4;             // k offset for h load (float4)
    const int uk = tid >> 3;                  // 0..31 : U k-row to load
    const int c4 = (tid & 7) * 4;             // local col offset (float4)
    const int ug = c4 >> 3;                   // gate group of loaded cols
    const int uj = c4 & 7;

    for (int kt = 0; kt < HH; kt += 32) {
        // h tile: hS[k][m] = hprev[m][kt+k]
        float4 hv4 = *(const float4*)(hprev + lm * HH + kt + kk);
        hS[kk + 0][lm] = hv4.x;
        hS[kk + 1][lm] = hv4.y;
        hS[kk + 2][lm] = hv4.z;
        hS[kk + 3][lm] = hv4.w;
        // U tile: uS[k][c] = U[kt+k][ g*H + n0 + j ]
        const float* urow = U + (size_t)(kt + uk) * G4H + ug * HH + n0 + uj;
        *(float4*)(&uS[uk][c4]) = *(const float4*)(urow);
        __syncthreads();
#pragma unroll
        for (int k = 0; k < 32; ++k) {
            float hv = hS[k][m];
            float4 uv = *(const float4*)(&uS[k][cbase]);
            acc0 += hv * uv.x;
            acc1 += hv * uv.y;
            acc2 += hv * uv.z;
            acc3 += hv * uv.w;
        }
        __syncthreads();
    }

    // z = h@U + xW_t  -> stash in smem for the gate-fusion phase
    {
        float a[4] = {acc0, acc1, acc2, acc3};
#pragma unroll
        for (int q = 0; q < 4; ++q) {
            int c = cbase + q;
            int g = c >> 3, j = c & 7;
            int n = g * HH + n0 + j;
            zS[m][c] = a[q] + g_xW[(size_t)(m * TT + t) * G4H + n];
        }
    }
    __syncthreads();

    // gates: 32 rows x 8 cols = 256 elements, one per thread
    {
        int mm = tid >> 3;
        int j = tid & 7;
        float iv = zS[mm][j];
        float fv = zS[mm][8 + j];
        float gv = zS[mm][16 + j];
        float ov = zS[mm][24 + j];
        float si = 1.f / (1.f + expf(-iv));
        float sf = 1.f / (1.f + expf(-fv));
        float tg = tanhf(gv);
        float so = 1.f / (1.f + expf(-ov));
        int idx = mm * HH + n0 + j;
        float cn = sf * g_c[idx] + si * tg;
        g_c[idx] = cn;
        float hn = so * tanhf(cn);
        g_h[(t + 1) & 1][idx] = hn;
        g_seq[(size_t)(mm * TT + t) * HH + n0 + j] = hn;
    }
}

// ---------------- launch ----------------
extern "C" void kernel_launch(void* const* d_in, const int* in_sizes, int n_in,
                              void* d_out, int out_size)
{
    const int*   x       = (const int*)d_in[0];
    const float* state_h = (const float*)d_in[1];
    const float* state_c = (const float*)d_in[2];
    const float* emb     = (const float*)d_in[3];
    const float* W       = (const float*)d_in[4];
    const float* U       = (const float*)d_in[5];
    const float* b       = (const float*)d_in[6];
    const float* dW      = (const float*)d_in[7];
    const float* db      = (const float*)d_in[8];
    float* out = (float*)d_out;

    float* xW_ptr  = nullptr;
    float* seq_ptr = nullptr;
    cudaGetSymbolAddress((void**)&xW_ptr,  g_xW);
    cudaGetSymbolAddress((void**)&seq_ptr, g_seq);

    // 1) load initial state
    init_state_kernel<<<64, 512>>>(state_h, state_c);

    // 2) xW = emb_table[x] @ W + b   (M=2048, N=4096, K=512, gathered A)
    {
        dim3 grid(G4H / 128, NROWS / 128);
        sgemm_kernel<true><<<grid, 256>>>(emb, x, W, b, xW_ptr, NROWS, G4H, EE, EE);
    }

    // 3) LSTM scan: 64 fused step kernels
    for (int t = 0; t < TT; ++t) {
        lstm_step_kernel<<<128, 256>>>(U, t);
    }

    // 4) logits = seq @ dense_W + dense_b  (M=2048, N=32000, K=1024)
    {
        dim3 grid(VV / 128, NROWS / 128);
        sgemm_kernel<false><<<grid, 256>>>(seq_ptr, nullptr, dW, db, out, NROWS, VV, HH, HH);
    }

    // 5) final h, c appended after logits
    float* out_h = out + (size_t)NROWS * VV;       // 65,536,000
    float* out_c = out_h + BB * HH;                // +32,768
    write_state_kernel<<<64, 512>>>(out_h, out_c);
}

// round 2
// speedup vs baseline: 1.0971x; 1.0971x over previous
#include <cuda_runtime.h>
#include <cuda_bf16.h>
#include <math.h>

// Problem constants
#define VV 32000
#define EE 512
#define HH 1024
#define BB 32
#define TT 64
#define G4H (4 * HH)          // 4096
#define NROWS (BB * TT)       // 2048
#define KSLICES 4
#define NCG 128               // column groups (each owns 8 h-cols x 4 gates = 32 z-cols)

// ---------------- scratch (no allocs allowed) ----------------
__device__ float g_xW[NROWS * G4H];        // [b*T+t, 4H] input projections (+bias)
__device__ float g_seq[NROWS * HH];        // [b*T+t, H] hidden states per step
__device__ float g_h[2][BB * HH];          // ping-pong hidden state
__device__ float g_c[BB * HH];             // cell state
__device__ float g_zpart[KSLICES * NCG * 32 * 32];  // split-K partials, layout [s][cg][c][m]
__device__ int   g_cnt[NCG];               // arrival counters (zero-init, reset by finisher)

// ---------------- init / finalize ----------------
__global__ void init_state_kernel(const float* __restrict__ h0, const float* __restrict__ c0) {
    int i = blockIdx.x * blockDim.x + threadIdx.x;
    if (i < BB * HH) {
        g_h[0][i] = h0[i];
        g_c[i] = c0[i];
    }
}

__global__ void write_state_kernel(float* __restrict__ out_h, float* __restrict__ out_c) {
    int i = blockIdx.x * blockDim.x + threadIdx.x;
    if (i < BB * HH) {
        out_h[i] = g_h[0][i];   // after 64 steps, latest h lives in buffer 0
        out_c[i] = g_c[i];
    }
}

// ---------------- generic fp32 SGEMM (prefetch-pipelined) ----------------
// C[M,N] = A[M,K] @ B[K,N] + bias[N]
// If GATHER: A row r is A + rowidx[r]*lda. Requires M%128==0, N%128==0, K%8==0.
template <bool GATHER>
__global__ __launch_bounds__(256, 2)
void sgemm_kernel(const float* __restrict__ A, const int* __restrict__ rowidx,
                  const float* __restrict__ B, const float* __restrict__ bias,
                  float* __restrict__ C, int M, int N, int K, int lda)
{
    constexpr int BM = 128, BN = 128, BK = 8, TM = 8, TN = 8;
    __shared__ float As[BK][BM];   // transposed A tile
    __shared__ float Bs[BK][BN];

    const int brow = blockIdx.y;
    const int bcol = blockIdx.x;
    const int tid = threadIdx.x;          // 256 threads
    const int tx = tid % 16;              // 16x16 thread grid
    const int ty = tid / 16;

    float acc[TM][TN];
#pragma unroll
    for (int i = 0; i < TM; ++i)
#pragma unroll
        for (int j = 0; j < TN; ++j) acc[i][j] = 0.f;

    const int a_r = tid >> 1;             // 0..127
    const int a_k = (tid & 1) * 4;        // 0 or 4
    const int b_k = tid >> 5;             // 0..7
    const int b_c = (tid & 31) * 4;       // 0..124

    const int grow = brow * BM + a_r;
    const float* Arow;
    if (GATHER) Arow = A + (size_t)rowidx[grow] * lda;
    else        Arow = A + (size_t)grow * lda;

    const float* Bbase = B + (size_t)bcol * BN;

    // prefetch first tiles
    float4 av = *(const float4*)(Arow + a_k);
    float4 bv = *(const float4*)(Bbase + (size_t)b_k * N + b_c);

    for (int kt = 0; kt < K; kt += BK) {
        As[a_k + 0][a_r] = av.x;
        As[a_k + 1][a_r] = av.y;
        As[a_k + 2][a_r] = av.z;
        As[a_k + 3][a_r] = av.w;
        *(float4*)(&Bs[b_k][b_c]) = bv;
        __syncthreads();

        // prefetch next tiles while computing on current ones
        if (kt + BK < K) {
            av = *(const float4*)(Arow + kt + BK + a_k);
            bv = *(const float4*)(Bbase + (size_t)(kt + BK + b_k) * N + b_c);
        }
#pragma unroll
        for (int k = 0; k < BK; ++k) {
            float ra[TM], rb[TN];
#pragma unroll
            for (int i = 0; i < TM; ++i) ra[i] = As[k][ty * TM + i];
#pragma unroll
            for (int j = 0; j < TN; ++j) rb[j] = Bs[k][tx * TN + j];
#pragma unroll
            for (int i = 0; i < TM; ++i)
#pragma unroll
                for (int j = 0; j < TN; ++j)
                    acc[i][j] += ra[i] * rb[j];
        }
        __syncthreads();
    }

    const int ccol0 = bcol * BN + tx * TN;
#pragma unroll
    for (int i = 0; i < TM; ++i) {
        size_t r = (size_t)(brow * BM + ty * TM + i);
        float* crow = C + r * (size_t)N + ccol0;
#pragma unroll
        for (int j = 0; j < TN; j += 4) {
            float4 v;
            v.x = acc[i][j + 0] + bias[ccol0 + j + 0];
            v.y = acc[i][j + 1] + bias[ccol0 + j + 1];
            v.z = acc[i][j + 2] + bias[ccol0 + j + 2];
            v.w = acc[i][j + 3] + bias[ccol0 + j + 3];
            *(float4*)(crow + j) = v;
        }
    }
}

// ---------------- fused LSTM step (split-K + last-block reduction) ----------------
// Grid: (KSLICES, NCG). Block (ks, cg) computes the 32x32 partial of
// z = h @ U over K slice [ks*256, ks*256+256) for column-group cg
// (h-cols [cg*8, cg*8+8) x 4 gates). Partials go to g_zpart; the last block
// to finish a column group sums the 4 partials in fixed order, adds xW,
// applies gate nonlinearities and updates h (ping-pong), c, seq.
__global__ __launch_bounds__(256)
void lstm_step_kernel(const float* __restrict__ U, int t)
{
    const int ks = blockIdx.x;                // k-slice 0..3
    const int cg = blockIdx.y;                // column group 0..127
    const int n0 = cg * 8;
    const int tid = threadIdx.x;              // 256 threads

    const float* __restrict__ hprev = g_h[t & 1];

    __shared__ float hS[32][33];              // [k][m], padded
    __shared__ float uS[32][32];              // [k][local c]
    __shared__ bool amLast;

    float acc0 = 0.f, acc1 = 0.f, acc2 = 0.f, acc3 = 0.f;
    const int m = tid & 31;                   // batch row this thread accumulates
    const int cbase = (tid >> 5) * 4;         // 4 local cols per thread

    const int lm = tid >> 3;                  // h row to load
    const int kk = (tid & 7) * 4;             // k offset for h load (float4)
    const int uk = tid >> 3;                  // U k-row to load
    const int c4 = (tid & 7) * 4;             // local col offset (float4)
    const int ug = c4 >> 3;                   // gate group of loaded cols
    const int uj = c4 & 7;

    const int kbeg = ks * (HH / KSLICES);     // 256-wide slice
    const int kend = kbeg + (HH / KSLICES);

    for (int kt = kbeg; kt < kend; kt += 32) {
        float4 hv4 = *(const float4*)(hprev + lm * HH + kt + kk);
        hS[kk + 0][lm] = hv4.x;
        hS[kk + 1][lm] = hv4.y;
        hS[kk + 2][lm] = hv4.z;
        hS[kk + 3][lm] = hv4.w;
        const float* urow = U + (size_t)(kt + uk) * G4H + ug * HH + n0 + uj;
        *(float4*)(&uS[uk][c4]) = *(const float4*)(urow);
        __syncthreads();
#pragma unroll
        for (int k = 0; k < 32; ++k) {
            float hv = hS[k][m];
            float4 uv = *(const float4*)(&uS[k][cbase]);
            acc0 += hv * uv.x;
            acc1 += hv * uv.y;
            acc2 += hv * uv.z;
            acc3 += hv * uv.w;
        }
        __syncthreads();
    }

    // write partial, layout [s][cg][c][m] (coalesced over m)
    {
        float* zp = g_zpart + ((size_t)(ks * NCG + cg)) * 1024;
        zp[(cbase + 0) * 32 + m] = acc0;
        zp[(cbase + 1) * 32 + m] = acc1;
        zp[(cbase + 2) * 32 + m] = acc2;
        zp[(cbase + 3) * 32 + m] = acc3;
    }
    __threadfence();
    __syncthreads();
    if (tid == 0) {
        int old = atomicAdd(&g_cnt[cg], 1);
        amLast = (old == KSLICES - 1);
    }
    __syncthreads();
    if (!amLast) return;
    __threadfence();

    // ----- finisher: reduce partials + gates + state update -----
    // thread (mm, j): mm = tid & 31 (batch row), j = tid >> 5 (h col 0..7)
    {
        const int mm = tid & 31;
        const int j = tid >> 5;

        float z[4];
#pragma unroll
        for (int g = 0; g < 4; ++g) {
            int c = g * 8 + j;
            float s = 0.f;
#pragma unroll
            for (int sl = 0; sl < KSLICES; ++sl)
                s += g_zpart[((size_t)(sl * NCG + cg)) * 1024 + c * 32 + mm];
            z[g] = s + g_xW[(size_t)(mm * TT + t) * G4H + g * HH + n0 + j];
        }

        float si = 1.f / (1.f + expf(-z[0]));
        float sf = 1.f / (1.f + expf(-z[1]));
        float tg = tanhf(z[2]);
        float so = 1.f / (1.f + expf(-z[3]));
        int idx = mm * HH + n0 + j;
        float cn = sf * g_c[idx] + si * tg;
        g_c[idx] = cn;
        float hn = so * tanhf(cn);
        g_h[(t + 1) & 1][idx] = hn;
        g_seq[(size_t)(mm * TT + t) * HH + n0 + j] = hn;
    }
    __syncthreads();
    if (tid == 0) g_cnt[cg] = 0;   // reset for next step / next graph replay
}

// ---------------- launch ----------------
extern "C" void kernel_launch(void* const* d_in, const int* in_sizes, int n_in,
                              void* d_out, int out_size)
{
    const int*   x       = (const int*)d_in[0];
    const float* state_h = (const float*)d_in[1];
    const float* state_c = (const float*)d_in[2];
    const float* emb     = (const float*)d_in[3];
    const float* W       = (const float*)d_in[4];
    const float* U       = (const float*)d_in[5];
    const float* b       = (const float*)d_in[6];
    const float* dW      = (const float*)d_in[7];
    const float* db      = (const float*)d_in[8];
    float* out = (float*)d_out;

    float* xW_ptr  = nullptr;
    float* seq_ptr = nullptr;
    cudaGetSymbolAddress((void**)&xW_ptr,  g_xW);
    cudaGetSymbolAddress((void**)&seq_ptr, g_seq);

    // 1) load initial state
    init_state_kernel<<<64, 512>>>(state_h, state_c);

    // 2) xW = emb_table[x] @ W + b   (M=2048, N=4096, K=512, gathered A)
    {
        dim3 grid(G4H / 128, NROWS / 128);
        sgemm_kernel<true><<<grid, 256>>>(emb, x, W, b, xW_ptr, NROWS, G4H, EE, EE);
    }

    // 3) LSTM scan: 64 fused split-K step kernels
    for (int t = 0; t < TT; ++t) {
        dim3 grid(KSLICES, NCG);
        lstm_step_kernel<<<grid, 256>>>(U, t);
    }

    // 4) logits = seq @ dense_W + dense_b  (M=2048, N=32000, K=1024)
    {
        dim3 grid(VV / 128, NROWS / 128);
        sgemm_kernel<false><<<grid, 256>>>(seq_ptr, nullptr, dW, db, out, NROWS, VV, HH, HH);
    }

    // 5) final h, c appended after logits
    float* out_h = out + (size_t)NROWS * VV;       // 65,536,000
    float* out_c = out_h + BB * HH;                // +32,768
    write_state_kernel<<<64, 512>>>(out_h, out_c);
}

// round 4
// speedup vs baseline: 1.3646x; 1.2438x over previous
#include <cuda_runtime.h>
#include <cuda_bf16.h>
#include <math.h>
#include <stdint.h>

// Problem constants
#define VV 32000
#define EE 512
#define HH 1024
#define BB 32
#define TT 64
#define G4H (4 * HH)          // 4096
#define NROWS (BB * TT)       // 2048

// LSTM step decomposition
#define KS 8                  // k slices (each 128 deep)
#define CG 32                 // column groups (each 32 hcols x 4 gates = 128 z-cols)

// ---------------- scratch (no allocs allowed) ----------------
__device__ float g_xW[NROWS * G4H];        // [b*T+t, 4H] input projections (+bias)
__device__ float g_seq[NROWS * HH];        // [b*T+t, H] hidden states per step
__device__ float g_h[2][BB * HH];          // ping-pong hidden state
__device__ float g_c[BB * HH];             // cell state
__device__ float g_zpart[KS * CG * 128 * 32];  // split-K partials, layout [ks][cg][c][m]
__device__ int   g_cnt[CG];                // arrival counters (zero-init; finisher resets)

// ---------------- init / finalize ----------------
__global__ void init_state_kernel(const float* __restrict__ h0, const float* __restrict__ c0) {
    int i = blockIdx.x * blockDim.x + threadIdx.x;
    if (i < BB * HH) {
        g_h[0][i] = h0[i];
        g_c[i] = c0[i];
    }
}

__global__ void write_state_kernel(float* __restrict__ out_h, float* __restrict__ out_c) {
    int i = blockIdx.x * blockDim.x + threadIdx.x;
    if (i < BB * HH) {
        out_h[i] = g_h[0][i];   // after 64 steps (even), latest h is in buffer 0
        out_c[i] = g_c[i];
    }
}

// ---------------- tf32 helpers ----------------
// cvt.rna.tf32.f32 writes a .b32 register holding the fp32 bit-pattern of the
// tf32-rounded value (low mantissa bits cleared).
__device__ __forceinline__ float to_tf32(float x) {
    uint32_t y;
    asm("cvt.rna.tf32.f32 %0, %1;" : "=r"(y) : "f"(x));
    return __uint_as_float(y);
}

__device__ __forceinline__ void mma_tf32(float* c, uint32_t a0, uint32_t a1, uint32_t a2, uint32_t a3,
                                         uint32_t b0, uint32_t b1) {
    asm volatile(
        "mma.sync.aligned.m16n8k8.row.col.f32.tf32.tf32.f32 "
        "{%0,%1,%2,%3}, {%4,%5,%6,%7}, {%8,%9}, {%0,%1,%2,%3};"
        : "+f"(c[0]), "+f"(c[1]), "+f"(c[2]), "+f"(c[3])
        : "r"(a0), "r"(a1), "r"(a2), "r"(a3), "r"(b0), "r"(b1));
}

// ---------------- tf32x2 GEMM (logits) ----------------
// C[M,N] = A[M,K] @ B[K,N] + bias[N], fp32-accurate on B via hi/lo tf32 split.
// BM=128, BN=128, BK=16; 8 warps; warp tile 64x32 via m16n8k8.
// Requires M%128==0, N%128==0, K%16==0.
__global__ __launch_bounds__(256, 1)
void tf32_gemm_kernel(const float* __restrict__ A, const float* __restrict__ B,
                      const float* __restrict__ bias, float* __restrict__ C,
                      int M, int N, int K)
{
    __shared__ float As[128][20];   // [m][k], pad 20 -> conflict-free frag loads
    __shared__ float Bh[16][136];   // [k][n] hi part
    __shared__ float Bl[16][136];   // [k][n] lo part

    const int tid = threadIdx.x;
    const int lane = tid & 31;
    const int wid = tid >> 5;
    const int wr = wid >> 2;          // 0..1 warp row
    const int wc = wid & 3;           // 0..3 warp col
    const int bm = blockIdx.y * 128;
    const int bn = blockIdx.x * 128;

    float acc[4][4][4];
#pragma unroll
    for (int i = 0; i < 4; ++i)
#pragma unroll
        for (int j = 0; j < 4; ++j)
#pragma unroll
            for (int r = 0; r < 4; ++r) acc[i][j][r] = 0.f;

    // gmem load mappings (2 float4 each for A and B per thread)
    // A: id = tid + i*256 -> m = id>>2, kq = (id&3)*4
    // B: id = tid + i*256 -> k = id>>5, n4 = (id&31)*4

    float4 pa[2], pb[2];
#pragma unroll
    for (int i = 0; i < 2; ++i) {
        int id = tid + i * 256;
        int m = id >> 2, kq = (id & 3) * 4;
        pa[i] = *(const float4*)(A + (size_t)(bm + m) * K + kq);
        int k = id >> 5, n4 = (id & 31) * 4;
        pb[i] = *(const float4*)(B + (size_t)k * N + bn + n4);
    }

    for (int kt = 0; kt < K; kt += 16) {
        // stash prefetched tiles to smem (with tf32 conversion / hi-lo split)
#pragma unroll
        for (int i = 0; i < 2; ++i) {
            int id = tid + i * 256;
            int m = id >> 2, kq = (id & 3) * 4;
            As[m][kq + 0] = to_tf32(pa[i].x);
            As[m][kq + 1] = to_tf32(pa[i].y);
            As[m][kq + 2] = to_tf32(pa[i].z);
            As[m][kq + 3] = to_tf32(pa[i].w);
            int k = id >> 5, n4 = (id & 31) * 4;
            float h0 = to_tf32(pb[i].x), h1 = to_tf32(pb[i].y);
            float h2 = to_tf32(pb[i].z), h3 = to_tf32(pb[i].w);
            Bh[k][n4 + 0] = h0; Bl[k][n4 + 0] = to_tf32(pb[i].x - h0);
            Bh[k][n4 + 1] = h1; Bl[k][n4 + 1] = to_tf32(pb[i].y - h1);
            Bh[k][n4 + 2] = h2; Bl[k][n4 + 2] = to_tf32(pb[i].z - h2);
            Bh[k][n4 + 3] = h3; Bl[k][n4 + 3] = to_tf32(pb[i].w - h3);
        }
        __syncthreads();

        // prefetch next k-tile
        if (kt + 16 < K) {
#pragma unroll
            for (int i = 0; i < 2; ++i) {
                int id = tid + i * 256;
                int m = id >> 2, kq = (id & 3) * 4;
                pa[i] = *(const float4*)(A + (size_t)(bm + m) * K + kt + 16 + kq);
                int k = id >> 5, n4 = (id & 31) * 4;
                pb[i] = *(const float4*)(B + (size_t)(kt + 16 + k) * N + bn + n4);
            }
        }

#pragma unroll
        for (int ks = 0; ks < 16; ks += 8) {
            // A fragments: 4 m-tiles
            uint32_t af[4][4];
#pragma unroll
            for (int mt = 0; mt < 4; ++mt) {
                int r0 = wr * 64 + mt * 16 + (lane >> 2);
                int kc = ks + (lane & 3);
                af[mt][0] = __float_as_uint(As[r0][kc]);
                af[mt][1] = __float_as_uint(As[r0 + 8][kc]);
                af[mt][2] = __float_as_uint(As[r0][kc + 4]);
                af[mt][3] = __float_as_uint(As[r0 + 8][kc + 4]);
            }
#pragma unroll
            for (int nt = 0; nt < 4; ++nt) {
                int c0 = wc * 32 + nt * 8 + (lane >> 2);
                int kc = ks + (lane & 3);
                uint32_t bh0 = __float_as_uint(Bh[kc][c0]);
                uint32_t bh1 = __float_as_uint(Bh[kc + 4][c0]);
                uint32_t bl0 = __float_as_uint(Bl[kc][c0]);
                uint32_t bl1 = __float_as_uint(Bl[kc + 4][c0]);
#pragma unroll
                for (int mt = 0; mt < 4; ++mt) {
                    mma_tf32(acc[mt][nt], af[mt][0], af[mt][1], af[mt][2], af[mt][3], bh0, bh1);
                    mma_tf32(acc[mt][nt], af[mt][0], af[mt][1], af[mt][2], af[mt][3], bl0, bl1);
                }
            }
        }
        __syncthreads();
    }

    // epilogue
#pragma unroll
    for (int mt = 0; mt < 4; ++mt) {
        int r0 = bm + wr * 64 + mt * 16 + (lane >> 2);
#pragma unroll
        for (int nt = 0; nt < 4; ++nt) {
            int col = bn + wc * 32 + nt * 8 + 2 * (lane & 3);
            float b0 = bias[col], b1 = bias[col + 1];
            float2 v0 = make_float2(acc[mt][nt][0] + b0, acc[mt][nt][1] + b1);
            float2 v1 = make_float2(acc[mt][nt][2] + b0, acc[mt][nt][3] + b1);
            *(float2*)(C + (size_t)r0 * N + col) = v0;
            *(float2*)(C + (size_t)(r0 + 8) * N + col) = v1;
        }
    }
}

// ---------------- fp32 SGEMM (xW, gathered) ----------------
template <bool GATHER>
__global__ __launch_bounds__(256, 2)
void sgemm_kernel(const float* __restrict__ A, const int* __restrict__ rowidx,
                  const float* __restrict__ B, const float* __restrict__ bias,
                  float* __restrict__ C, int M, int N, int K, int lda)
{
    constexpr int BM = 128, BN = 128, BK = 8, TM = 8, TN = 8;
    __shared__ float As[BK][BM];
    __shared__ float Bs[BK][BN];

    const int brow = blockIdx.y;
    const int bcol = blockIdx.x;
    const int tid = threadIdx.x;
    const int tx = tid % 16;
    const int ty = tid / 16;

    float acc[TM][TN];
#pragma unroll
    for (int i = 0; i < TM; ++i)
#pragma unroll
        for (int j = 0; j < TN; ++j) acc[i][j] = 0.f;

    const int a_r = tid >> 1;
    const int a_k = (tid & 1) * 4;
    const int b_k = tid >> 5;
    const int b_c = (tid & 31) * 4;

    const int grow = brow * BM + a_r;
    const float* Arow;
    if (GATHER) Arow = A + (size_t)rowidx[grow] * lda;
    else        Arow = A + (size_t)grow * lda;
    const float* Bbase = B + (size_t)bcol * BN;

    float4 av = *(const float4*)(Arow + a_k);
    float4 bv = *(const float4*)(Bbase + (size_t)b_k * N + b_c);

    for (int kt = 0; kt < K; kt += BK) {
        As[a_k + 0][a_r] = av.x;
        As[a_k + 1][a_r] = av.y;
        As[a_k + 2][a_r] = av.z;
        As[a_k + 3][a_r] = av.w;
        *(float4*)(&Bs[b_k][b_c]) = bv;
        __syncthreads();
        if (kt + BK < K) {
            av = *(const float4*)(Arow + kt + BK + a_k);
            bv = *(const float4*)(Bbase + (size_t)(kt + BK + b_k) * N + b_c);
        }
#pragma unroll
        for (int k = 0; k < BK; ++k) {
            float ra[TM], rb[TN];
#pragma unroll
            for (int i = 0; i < TM; ++i) ra[i] = As[k][ty * TM + i];
#pragma unroll
            for (int j = 0; j < TN; ++j) rb[j] = Bs[k][tx * TN + j];
#pragma unroll
            for (int i = 0; i < TM; ++i)
#pragma unroll
                for (int j = 0; j < TN; ++j)
                    acc[i][j] += ra[i] * rb[j];
        }
        __syncthreads();
    }

    const int ccol0 = bcol * BN + tx * TN;
#pragma unroll
    for (int i = 0; i < TM; ++i) {
        size_t r = (size_t)(brow * BM + ty * TM + i);
        float* crow = C + r * (size_t)N + ccol0;
#pragma unroll
        for (int j = 0; j < TN; j += 4) {
            float4 v;
            v.x = acc[i][j + 0] + bias[ccol0 + j + 0];
            v.y = acc[i][j + 1] + bias[ccol0 + j + 1];
            v.z = acc[i][j + 2] + bias[ccol0 + j + 2];
            v.w = acc[i][j + 3] + bias[ccol0 + j + 3];
            *(float4*)(crow + j) = v;
        }
    }
}

// ---------------- fused LSTM step (split-K, 4x4 microtile, last-block finisher) ----------------
// Grid (KS, CG). Block (ks, cg): 32 m x 128 local z-cols, K slice of 128.
// Local col c (0..127) -> global z col = (c>>5)*HH + cg*32 + (c&31)
// (each group owns 32 hcols x all 4 gates, so the finisher can fuse the gates).
__global__ __launch_bounds__(256)
void lstm_step_kernel(const float* __restrict__ U, int t)
{
    const int ks = blockIdx.x;
    const int cg = blockIdx.y;
    const int tid = threadIdx.x;
    const int lane = tid & 31;

    const float* __restrict__ hprev = g_h[t & 1];

    __shared__ float hS[16][36];    // [k][m]
    __shared__ float uS[16][136];   // [k][local c]
    __shared__ bool amLast;

    const int tm = (tid >> 5) * 4;  // 4 m rows per thread (warp id * 4)
    const int tc = lane * 4;        // 4 local cols per thread

    float acc[4][4];                // [cc][mm]
#pragma unroll
    for (int i = 0; i < 4; ++i)
#pragma unroll
        for (int j = 0; j < 4; ++j) acc[i][j] = 0.f;

    const int kbeg = ks * (HH / KS);   // 128-wide slice

    for (int kt = 0; kt < HH / KS; kt += 16) {
        // load h tile: hS[k][m] = hprev[m][kbeg+kt+k]  (threads 0..127)
        if (tid < 128) {
            int m = tid >> 2, kq = (tid & 3) * 4;
            float4 hv = *(const float4*)(hprev + m * HH + kbeg + kt + kq);
            hS[kq + 0][m] = hv.x;
            hS[kq + 1][m] = hv.y;
            hS[kq + 2][m] = hv.z;
            hS[kq + 3][m] = hv.w;
        }
        // load U tile: uS[k][c], c -> gate (c>>5), hcol cg*32 + (c&31)
#pragma unroll
        for (int i = 0; i < 2; ++i) {
            int id = tid + i * 256;
            int k = id >> 5, n4 = (id & 31) * 4;
            int col = (n4 >> 5) * HH + cg * 32 + (n4 & 31);
            *(float4*)(&uS[k][n4]) = *(const float4*)(U + (size_t)(kbeg + kt + k) * G4H + col);
        }
        __syncthreads();
#pragma unroll
        for (int k = 0; k < 16; ++k) {
            float4 hv = *(const float4*)(&hS[k][tm]);   // broadcast within warp
            float4 uv = *(const float4*)(&uS[k][tc]);
            float hvv[4] = {hv.x, hv.y, hv.z, hv.w};
            float uvv[4] = {uv.x, uv.y, uv.z, uv.w};
#pragma unroll
            for (int cc = 0; cc < 4; ++cc)
#pragma unroll
                for (int mm = 0; mm < 4; ++mm)
                    acc[cc][mm] += uvv[cc] * hvv[mm];
        }
        __syncthreads();
    }

    // write partials: layout [ks][cg][c][m], float4 over m
    {
        float* zp = g_zpart + ((size_t)(ks * CG + cg)) * 128 * 32;
#pragma unroll
        for (int cc = 0; cc < 4; ++cc) {
            float4 v = make_float4(acc[cc][0], acc[cc][1], acc[cc][2], acc[cc][3]);
            *(float4*)(zp + (tc + cc) * 32 + tm) = v;
        }
    }
    __threadfence();
    __syncthreads();
    if (tid == 0) {
        int old = atomicAdd(&g_cnt[cg], 1);
        amLast = (old == KS - 1);
    }
    __syncthreads();
    if (!amLast) return;
    __threadfence();

    // ----- finisher: reduce KS partials + gates + state update -----
    // thread: j = hcol within group (0..31), mq = m quad (0..7)
    {
        const int j = tid & 31;
        const int mq = tid >> 5;
        const int hcol = cg * 32 + j;

        float4 z[4];
#pragma unroll
        for (int g = 0; g < 4; ++g) {
            float4 s = make_float4(0.f, 0.f, 0.f, 0.f);
#pragma unroll
            for (int sl = 0; sl < KS; ++sl) {
                const float4 p = *(const float4*)(g_zpart +
                    ((size_t)(sl * CG + cg)) * 128 * 32 + (g * 32 + j) * 32 + mq * 4);
                s.x += p.x; s.y += p.y; s.z += p.z; s.w += p.w;
            }
            z[g] = s;
        }

#pragma unroll
        for (int mm = 0; mm < 4; ++mm) {
            int m = mq * 4 + mm;
            const float* xw = g_xW + (size_t)(m * TT + t) * G4H;
            float zi = ((const float*)&z[0])[mm] + xw[0 * HH + hcol];
            float zf = ((const float*)&z[1])[mm] + xw[1 * HH + hcol];
            float zg = ((const float*)&z[2])[mm] + xw[2 * HH + hcol];
            float zo = ((const float*)&z[3])[mm] + xw[3 * HH + hcol];

            float si = 1.f / (1.f + expf(-zi));
            float sf = 1.f / (1.f + expf(-zf));
            float tg = tanhf(zg);
            float so = 1.f / (1.f + expf(-zo));
            int idx = m * HH + hcol;
            float cn = sf * g_c[idx] + si * tg;
            g_c[idx] = cn;
            float hn = so * tanhf(cn);
            g_h[(t + 1) & 1][idx] = hn;
            g_seq[(size_t)(m * TT + t) * HH + hcol] = hn;
        }
    }
    __syncthreads();
    if (tid == 0) g_cnt[cg] = 0;   // reset for next step / next replay
}

// ---------------- launch ----------------
extern "C" void kernel_launch(void* const* d_in, const int* in_sizes, int n_in,
                              void* d_out, int out_size)
{
    const int*   x       = (const int*)d_in[0];
    const float* state_h = (const float*)d_in[1];
    const float* state_c = (const float*)d_in[2];
    const float* emb     = (const float*)d_in[3];
    const float* W       = (const float*)d_in[4];
    const float* U       = (const float*)d_in[5];
    const float* b       = (const float*)d_in[6];
    const float* dW      = (const float*)d_in[7];
    const float* db      = (const float*)d_in[8];
    float* out = (float*)d_out;

    float* xW_ptr  = nullptr;
    float* seq_ptr = nullptr;
    cudaGetSymbolAddress((void**)&xW_ptr,  g_xW);
    cudaGetSymbolAddress((void**)&seq_ptr, g_seq);

    // 1) load initial state
    init_state_kernel<<<64, 512>>>(state_h, state_c);

    // 2) xW = emb_table[x] @ W + b   (M=2048, N=4096, K=512, gathered A, fp32)
    {
        dim3 grid(G4H / 128, NROWS / 128);
        sgemm_kernel<true><<<grid, 256>>>(emb, x, W, b, xW_ptr, NROWS, G4H, EE, EE);
    }

    // 3) LSTM scan: 64 fused split-K step kernels (fp32)
    for (int t = 0; t < TT; ++t) {
        dim3 grid(KS, CG);
        lstm_step_kernel<<<grid, 256>>>(U, t);
    }

    // 4) logits = seq @ dense_W + dense_b  (M=2048, N=32000, K=1024, tf32x2 tensor cores)
    {
        dim3 grid(VV / 128, NROWS / 128);
        tf32_gemm_kernel<<<grid, 256>>>(seq_ptr, dW, db, out, NROWS, VV, HH);
    }

    // 5) final h, c appended after logits
    float* out_h = out + (size_t)NROWS * VV;       // 65,536,000
    float* out_c = out_h + BB * HH;                // +32,768
    write_state_kernel<<<64, 512>>>(out_h, out_c);
}

// round 7
// speedup vs baseline: 1.4989x; 1.0984x over previous
#include <cuda_runtime.h>
#include <cuda_bf16.h>
#include <math.h>
#include <stdint.h>

// Problem constants
#define VV 32000
#define EE 512
#define HH 1024
#define BB 32
#define TT 64
#define G4H (4 * HH)          // 4096
#define NROWS (BB * TT)       // 2048

#define NBLK 128              // persistent blocks (each owns 8 hcols x 4 gates)
#define NTHR 256

// padded row strides (MUST be multiples of 4 for float4 access)
#define HPAD 36
#define ZPAD 36

// ---------------- scratch (no allocs allowed) ----------------
__device__ float g_xW[NROWS * G4H];        // [b*T+t, 4H] input projections (+bias)
__device__ float g_seq[NROWS * HH];        // [b*T+t, H] hidden states per step
__device__ float g_h[2][BB * HH];          // ping-pong hidden state
__device__ float g_c[BB * HH];             // cell state
__device__ int   g_bar;                    // grid barrier counter (reset by init kernel)

// ---------------- init / finalize ----------------
__global__ void init_state_kernel(const float* __restrict__ h0, const float* __restrict__ c0) {
    int i = blockIdx.x * blockDim.x + threadIdx.x;
    if (i < BB * HH) {
        g_h[0][i] = h0[i];
        g_c[i] = c0[i];
    }
    if (i == 0) g_bar = 0;
}

__global__ void write_state_kernel(float* __restrict__ out_h, float* __restrict__ out_c) {
    int i = blockIdx.x * blockDim.x + threadIdx.x;
    if (i < BB * HH) {
        out_h[i] = g_h[0][i];   // after 64 steps (even), latest h is in buffer 0
        out_c[i] = g_c[i];
    }
}

// ---------------- tf32 helpers ----------------
__device__ __forceinline__ float to_tf32(float x) {
    uint32_t y;
    asm("cvt.rna.tf32.f32 %0, %1;" : "=r"(y) : "f"(x));
    return __uint_as_float(y);
}

__device__ __forceinline__ void mma_tf32(float* c, uint32_t a0, uint32_t a1, uint32_t a2, uint32_t a3,
                                         uint32_t b0, uint32_t b1) {
    asm volatile(
        "mma.sync.aligned.m16n8k8.row.col.f32.tf32.tf32.f32 "
        "{%0,%1,%2,%3}, {%4,%5,%6,%7}, {%8,%9}, {%0,%1,%2,%3};"
        : "+f"(c[0]), "+f"(c[1]), "+f"(c[2]), "+f"(c[3])
        : "r"(a0), "r"(a1), "r"(a2), "r"(a3), "r"(b0), "r"(b1));
}

// ---------------- tf32x2 GEMM (logits) ----------------
// C[M,N] = A[M,K] @ B[K,N] + bias[N], fp32-accurate on B via hi/lo tf32 split.
__global__ __launch_bounds__(256, 1)
void tf32_gemm_kernel(const float* __restrict__ A, const float* __restrict__ B,
                      const float* __restrict__ bias, float* __restrict__ C,
                      int M, int N, int K)
{
    __shared__ float As[128][20];
    __shared__ float Bh[16][136];
    __shared__ float Bl[16][136];

    const int tid = threadIdx.x;
    const int lane = tid & 31;
    const int wid = tid >> 5;
    const int wr = wid >> 2;
    const int wc = wid & 3;
    const int bm = blockIdx.y * 128;
    const int bn = blockIdx.x * 128;

    float acc[4][4][4];
#pragma unroll
    for (int i = 0; i < 4; ++i)
#pragma unroll
        for (int j = 0; j < 4; ++j)
#pragma unroll
            for (int r = 0; r < 4; ++r) acc[i][j][r] = 0.f;

    float4 pa[2], pb[2];
#pragma unroll
    for (int i = 0; i < 2; ++i) {
        int id = tid + i * 256;
        int m = id >> 2, kq = (id & 3) * 4;
        pa[i] = *(const float4*)(A + (size_t)(bm + m) * K + kq);
        int k = id >> 5, n4 = (id & 31) * 4;
        pb[i] = *(const float4*)(B + (size_t)k * N + bn + n4);
    }

    for (int kt = 0; kt < K; kt += 16) {
#pragma unroll
        for (int i = 0; i < 2; ++i) {
            int id = tid + i * 256;
            int m = id >> 2, kq = (id & 3) * 4;
            As[m][kq + 0] = to_tf32(pa[i].x);
            As[m][kq + 1] = to_tf32(pa[i].y);
            As[m][kq + 2] = to_tf32(pa[i].z);
            As[m][kq + 3] = to_tf32(pa[i].w);
            int k = id >> 5, n4 = (id & 31) * 4;
            float h0 = to_tf32(pb[i].x), h1 = to_tf32(pb[i].y);
            float h2 = to_tf32(pb[i].z), h3 = to_tf32(pb[i].w);
            Bh[k][n4 + 0] = h0; Bl[k][n4 + 0] = to_tf32(pb[i].x - h0);
            Bh[k][n4 + 1] = h1; Bl[k][n4 + 1] = to_tf32(pb[i].y - h1);
            Bh[k][n4 + 2] = h2; Bl[k][n4 + 2] = to_tf32(pb[i].z - h2);
            Bh[k][n4 + 3] = h3; Bl[k][n4 + 3] = to_tf32(pb[i].w - h3);
        }
        __syncthreads();

        if (kt + 16 < K) {
#pragma unroll
            for (int i = 0; i < 2; ++i) {
                int id = tid + i * 256;
                int m = id >> 2, kq = (id & 3) * 4;
                pa[i] = *(const float4*)(A + (size_t)(bm + m) * K + kt + 16 + kq);
                int k = id >> 5, n4 = (id & 31) * 4;
                pb[i] = *(const float4*)(B + (size_t)(kt + 16 + k) * N + bn + n4);
            }
        }

#pragma unroll
        for (int ks = 0; ks < 16; ks += 8) {
            uint32_t af[4][4];
#pragma unroll
            for (int mt = 0; mt < 4; ++mt) {
                int r0 = wr * 64 + mt * 16 + (lane >> 2);
                int kc = ks + (lane & 3);
                af[mt][0] = __float_as_uint(As[r0][kc]);
                af[mt][1] = __float_as_uint(As[r0 + 8][kc]);
                af[mt][2] = __float_as_uint(As[r0][kc + 4]);
                af[mt][3] = __float_as_uint(As[r0 + 8][kc + 4]);
            }
#pragma unroll
            for (int nt = 0; nt < 4; ++nt) {
                int c0 = wc * 32 + nt * 8 + (lane >> 2);
                int kc = ks + (lane & 3);
                uint32_t bh0 = __float_as_uint(Bh[kc][c0]);
                uint32_t bh1 = __float_as_uint(Bh[kc + 4][c0]);
                uint32_t bl0 = __float_as_uint(Bl[kc][c0]);
                uint32_t bl1 = __float_as_uint(Bl[kc + 4][c0]);
#pragma unroll
                for (int mt = 0; mt < 4; ++mt) {
                    mma_tf32(acc[mt][nt], af[mt][0], af[mt][1], af[mt][2], af[mt][3], bh0, bh1);
                    mma_tf32(acc[mt][nt], af[mt][0], af[mt][1], af[mt][2], af[mt][3], bl0, bl1);
                }
            }
        }
        __syncthreads();
    }

#pragma unroll
    for (int mt = 0; mt < 4; ++mt) {
        int r0 = bm + wr * 64 + mt * 16 + (lane >> 2);
#pragma unroll
        for (int nt = 0; nt < 4; ++nt) {
            int col = bn + wc * 32 + nt * 8 + 2 * (lane & 3);
            float b0 = bias[col], b1 = bias[col + 1];
            float2 v0 = make_float2(acc[mt][nt][0] + b0, acc[mt][nt][1] + b1);
            float2 v1 = make_float2(acc[mt][nt][2] + b0, acc[mt][nt][3] + b1);
            *(float2*)(C + (size_t)r0 * N + col) = v0;
            *(float2*)(C + (size_t)(r0 + 8) * N + col) = v1;
        }
    }
}

// ---------------- fp32 SGEMM (xW, gathered) ----------------
template <bool GATHER>
__global__ __launch_bounds__(256, 2)
void sgemm_kernel(const float* __restrict__ A, const int* __restrict__ rowidx,
                  const float* __restrict__ B, const float* __restrict__ bias,
                  float* __restrict__ C, int M, int N, int K, int lda)
{
    constexpr int BM = 128, BN = 128, BK = 8, TM = 8, TN = 8;
    __shared__ float As[BK][BM];
    __shared__ float Bs[BK][BN];

    const int brow = blockIdx.y;
    const int bcol = blockIdx.x;
    const int tid = threadIdx.x;
    const int tx = tid % 16;
    const int ty = tid / 16;

    float acc[TM][TN];
#pragma unroll
    for (int i = 0; i < TM; ++i)
#pragma unroll
        for (int j = 0; j < TN; ++j) acc[i][j] = 0.f;

    const int a_r = tid >> 1;
    const int a_k = (tid & 1) * 4;
    const int b_k = tid >> 5;
    const int b_c = (tid & 31) * 4;

    const int grow = brow * BM + a_r;
    const float* Arow;
    if (GATHER) Arow = A + (size_t)rowidx[grow] * lda;
    else        Arow = A + (size_t)grow * lda;
    const float* Bbase = B + (size_t)bcol * BN;

    float4 av = *(const float4*)(Arow + a_k);
    float4 bv = *(const float4*)(Bbase + (size_t)b_k * N + b_c);

    for (int kt = 0; kt < K; kt += BK) {
        As[a_k + 0][a_r] = av.x;
        As[a_k + 1][a_r] = av.y;
        As[a_k + 2][a_r] = av.z;
        As[a_k + 3][a_r] = av.w;
        *(float4*)(&Bs[b_k][b_c]) = bv;
        __syncthreads();
        if (kt + BK < K) {
            av = *(const float4*)(Arow + kt + BK + a_k);
            bv = *(const float4*)(Bbase + (size_t)(kt + BK + b_k) * N + b_c);
        }
#pragma unroll
        for (int k = 0; k < BK; ++k) {
            float ra[TM], rb[TN];
#pragma unroll
            for (int i = 0; i < TM; ++i) ra[i] = As[k][ty * TM + i];
#pragma unroll
            for (int j = 0; j < TN; ++j) rb[j] = Bs[k][tx * TN + j];
#pragma unroll
            for (int i = 0; i < TM; ++i)
#pragma unroll
                for (int j = 0; j < TN; ++j)
                    acc[i][j] += ra[i] * rb[j];
        }
        __syncthreads();
    }

    const int ccol0 = bcol * BN + tx * TN;
#pragma unroll
    for (int i = 0; i < TM; ++i) {
        size_t r = (size_t)(brow * BM + ty * TM + i);
        float* crow = C + r * (size_t)N + ccol0;
#pragma unroll
        for (int j = 0; j < TN; j += 4) {
            float4 v;
            v.x = acc[i][j + 0] + bias[ccol0 + j + 0];
            v.y = acc[i][j + 1] + bias[ccol0 + j + 1];
            v.z = acc[i][j + 2] + bias[ccol0 + j + 2];
            v.w = acc[i][j + 3] + bias[ccol0 + j + 3];
            *(float4*)(crow + j) = v;
        }
    }
}

// ---------------- persistent LSTM scan ----------------
// One launch for all 64 steps. 128 blocks (1/SM, 128 <= 148 SMs so all are
// co-resident in wave 1 -> the spin barrier cannot deadlock). Block bx owns
// hcols [bx*8, bx*8+8) (32 z-cols across 4 gates); its U slice [1024][32]
// stays in smem for the whole scan (U read from DRAM exactly once).
//
// Dynamic smem layout (floats):
//   uS [1024*32]            = 131072 B
//   hS [256][HPAD]          =  36864 B   (transposed h tile, [k][m], HPAD=36)
//   zS [4][32][ZPAD]        =  18432 B   (k-slice partials, [slice][m][c])
#define SCAN_SMEM_BYTES ((1024*32 + 256*HPAD + 4*32*ZPAD) * 4)

__global__ __launch_bounds__(NTHR, 1)
void lstm_scan_kernel(const float* __restrict__ U)
{
    extern __shared__ float sm[];
    float* uS = sm;                    // [k][32]
    float* hS = sm + 1024 * 32;        // [k][HPAD]
    float* zS = hS + 256 * HPAD;       // [slice][m][ZPAD]

    const int bx = blockIdx.x;         // 0..127
    const int tid = threadIdx.x;

    // ---- load U slice once: uS[k][c], c = g*8+j -> global col g*H + bx*8 + j
    for (int i = tid; i < 1024 * 8; i += NTHR) {
        int k = i >> 3;
        int c4 = (i & 7) * 4;
        int g = c4 >> 3;
        int j = c4 & 7;
        float4 v = *(const float4*)(U + (size_t)k * G4H + g * HH + bx * 8 + j);
        *(float4*)(uS + k * 32 + c4) = v;
    }

    // ---- cell state in register: thread owns (om, oj)
    const int om = tid >> 3;           // 0..31 batch row
    const int oj = tid & 7;            // 0..7 local hcol
    const int ohcol = bx * 8 + oj;
    float creg = g_c[om * HH + ohcol];

    // ---- compute-phase indices
    const int ks = tid >> 6;           // 0..3 k-slice
    const int tq = tid & 63;
    const int mg = tq >> 3;            // m base = mg*4
    const int cq = tq & 7;             // c base = cq*4

    for (int t = 0; t < TT; ++t) {
        const float* __restrict__ hprev = g_h[t & 1];

        float acc[4][4];               // [mi][ci]
#pragma unroll
        for (int i = 0; i < 4; ++i)
#pragma unroll
            for (int j = 0; j < 4; ++j) acc[i][j] = 0.f;

        for (int kt = 0; kt < HH; kt += 256) {
            __syncthreads();           // prior readers of hS done
            // stage h tile transposed: hS[k][m] = hprev[m][kt+k]
#pragma unroll
            for (int i = 0; i < 8; ++i) {
                int id = tid + i * NTHR;
                int m = id >> 6;               // 0..31
                int k4 = id & 63;              // 0..63 (float4 along k)
                float4 v = *(const float4*)(hprev + m * HH + kt + k4 * 4);
                hS[(k4 * 4 + 0) * HPAD + m] = v.x;
                hS[(k4 * 4 + 1) * HPAD + m] = v.y;
                hS[(k4 * 4 + 2) * HPAD + m] = v.z;
                hS[(k4 * 4 + 3) * HPAD + m] = v.w;
            }
            __syncthreads();

            const float* hbase = hS + (ks * 64) * HPAD;
            const float* ubase = uS + (size_t)(kt + ks * 64) * 32;
#pragma unroll 8
            for (int k = 0; k < 64; ++k) {
                float4 hv = *(const float4*)(hbase + k * HPAD + mg * 4);
                float4 uv = *(const float4*)(ubase + k * 32 + cq * 4);
                float hvv[4] = {hv.x, hv.y, hv.z, hv.w};
                float uvv[4] = {uv.x, uv.y, uv.z, uv.w};
#pragma unroll
                for (int mi = 0; mi < 4; ++mi)
#pragma unroll
                    for (int ci = 0; ci < 4; ++ci)
                        acc[mi][ci] += hvv[mi] * uvv[ci];
            }
        }

        // ---- write slice partials
        __syncthreads();               // gate-phase of prev step done reading zS
#pragma unroll
        for (int mi = 0; mi < 4; ++mi) {
            float4 v = make_float4(acc[mi][0], acc[mi][1], acc[mi][2], acc[mi][3]);
            *(float4*)(zS + ((size_t)ks * 32 + mg * 4 + mi) * ZPAD + cq * 4) = v;
        }
        __syncthreads();

        // ---- gate fusion + state update for (om, ohcol)
        {
            float z[4];
#pragma unroll
            for (int g = 0; g < 4; ++g) {
                int c = g * 8 + oj;
                float s = 0.f;
#pragma unroll
                for (int sl = 0; sl < 4; ++sl)
                    s += zS[((size_t)sl * 32 + om) * ZPAD + c];
                z[g] = s + g_xW[(size_t)(om * TT + t) * G4H + g * HH + ohcol];
            }
            float si = 1.f / (1.f + expf(-z[0]));
            float sf = 1.f / (1.f + expf(-z[1]));
            float tg = tanhf(z[2]);
            float so = 1.f / (1.f + expf(-z[3]));
            creg = sf * creg + si * tg;
            float hn = so * tanhf(creg);
            g_h[(t + 1) & 1][om * HH + ohcol] = hn;
            g_seq[(size_t)(om * TT + t) * HH + ohcol] = hn;
        }

        // ---- grid barrier (release h writes, wait for all blocks)
        __threadfence();
        __syncthreads();
        if (tid == 0) {
            atomicAdd(&g_bar, 1);
            int target = NBLK * (t + 1);
            while (atomicAdd(&g_bar, 0) < target) { __nanosleep(20); }
        }
        __syncthreads();
        __threadfence();
    }

    // ---- write back cell state
    g_c[om * HH + ohcol] = creg;
}

// ---------------- launch ----------------
extern "C" void kernel_launch(void* const* d_in, const int* in_sizes, int n_in,
                              void* d_out, int out_size)
{
    const int*   x       = (const int*)d_in[0];
    const float* state_h = (const float*)d_in[1];
    const float* state_c = (const float*)d_in[2];
    const float* emb     = (const float*)d_in[3];
    const float* W       = (const float*)d_in[4];
    const float* U       = (const float*)d_in[5];
    const float* b       = (const float*)d_in[6];
    const float* dW      = (const float*)d_in[7];
    const float* db      = (const float*)d_in[8];
    float* out = (float*)d_out;

    float* xW_ptr  = nullptr;
    float* seq_ptr = nullptr;
    cudaGetSymbolAddress((void**)&xW_ptr,  g_xW);
    cudaGetSymbolAddress((void**)&seq_ptr, g_seq);

    // unconditional (no static guards — harness contract); idempotent + capture-safe
    cudaFuncSetAttribute(lstm_scan_kernel,
                         cudaFuncAttributeMaxDynamicSharedMemorySize, SCAN_SMEM_BYTES);

    // 1) load initial state + reset barrier
    init_state_kernel<<<64, 512>>>(state_h, state_c);

    // 2) xW = emb_table[x] @ W + b   (M=2048, N=4096, K=512, gathered A, fp32)
    {
        dim3 grid(G4H / 128, NROWS / 128);
        sgemm_kernel<true><<<grid, 256>>>(emb, x, W, b, xW_ptr, NROWS, G4H, EE, EE);
    }

    // 3) LSTM scan: single persistent cooperative kernel
    lstm_scan_kernel<<<NBLK, NTHR, SCAN_SMEM_BYTES>>>(U);

    // 4) logits = seq @ dense_W + dense_b  (tf32x2 tensor cores)
    {
        dim3 grid(VV / 128, NROWS / 128);
        tf32_gemm_kernel<<<grid, 256>>>(seq_ptr, dW, db, out, NROWS, VV, HH);
    }

    // 5) final h, c appended after logits
    float* out_h = out + (size_t)NROWS * VV;       // 65,536,000
    float* out_c = out_h + BB * HH;                // +32,768
    write_state_kernel<<<64, 512>>>(out_h, out_c);
}

// round 9
// speedup vs baseline: 1.5675x; 1.0458x over previous
#include <cuda_runtime.h>
#include <cuda_bf16.h>
#include <math.h>
#include <stdint.h>

// Problem constants
#define VV 32000
#define EE 512
#define HH 1024
#define BB 32
#define TT 64
#define G4H (4 * HH)          // 4096
#define NROWS (BB * TT)       // 2048

#define NBLK 128              // persistent blocks (each owns 8 hcols x 4 gates)
#define NTHR 512              // 16 warps: hide LDS latency, overlap LDS+FMA pipes

// padded row strides (MUST be multiples of 4 for float4 access)
#define HPAD 36
#define ZPAD 36
#define NSL  8                // k sub-slices (cyclic within each staged tile)

// ---------------- scratch (no allocs allowed) ----------------
__device__ float g_xW[NROWS * G4H];        // [b*T+t, 4H] input projections (+bias)
__device__ float g_seq[NROWS * HH];        // [b*T+t, H] hidden states (tf32-pre-rounded)
__device__ float g_h[2][BB * HH];          // ping-pong hidden state (full fp32)
__device__ float g_c[BB * HH];             // cell state
__device__ int   g_bar;                    // grid barrier counter (reset by init kernel)
__device__ float g_Bh[(size_t)HH * VV];    // dense_W tf32 hi part
__device__ float g_Bl[(size_t)HH * VV];    // dense_W tf32 lo part

// ---------------- init / finalize ----------------
__global__ void init_state_kernel(const float* __restrict__ h0, const float* __restrict__ c0) {
    int i = blockIdx.x * blockDim.x + threadIdx.x;
    if (i < BB * HH) {
        g_h[0][i] = h0[i];
        g_c[i] = c0[i];
    }
    if (i == 0) g_bar = 0;
}

__global__ void write_state_kernel(float* __restrict__ out_h, float* __restrict__ out_c) {
    int i = blockIdx.x * blockDim.x + threadIdx.x;
    if (i < BB * HH) {
        out_h[i] = g_h[0][i];   // after 64 steps (even), latest h is in buffer 0
        out_c[i] = g_c[i];
    }
}

// ---------------- tf32 helpers ----------------
__device__ __forceinline__ float to_tf32(float x) {
    uint32_t y;
    asm("cvt.rna.tf32.f32 %0, %1;" : "=r"(y) : "f"(x));
    return __uint_as_float(y);
}

__device__ __forceinline__ void mma_tf32(float* c, uint32_t a0, uint32_t a1, uint32_t a2, uint32_t a3,
                                         uint32_t b0, uint32_t b1) {
    asm volatile(
        "mma.sync.aligned.m16n8k8.row.col.f32.tf32.tf32.f32 "
        "{%0,%1,%2,%3}, {%4,%5,%6,%7}, {%8,%9}, {%0,%1,%2,%3};"
        : "+f"(c[0]), "+f"(c[1]), "+f"(c[2]), "+f"(c[3])
        : "r"(a0), "r"(a1), "r"(a2), "r"(a3), "r"(b0), "r"(b1));
}

// ---------------- B hi/lo pre-split (dense_W) ----------------
__global__ void split_b_kernel(const float* __restrict__ B) {
    const size_t n4 = (size_t)HH * VV / 4;
    size_t i = (size_t)blockIdx.x * blockDim.x + threadIdx.x;
    const size_t stride = (size_t)gridDim.x * blockDim.x;
    const float4* B4 = (const float4*)B;
    float4* H4 = (float4*)g_Bh;
    float4* L4 = (float4*)g_Bl;
    for (; i < n4; i += stride) {
        float4 v = B4[i];
        float4 h, l;
        h.x = to_tf32(v.x); l.x = to_tf32(v.x - h.x);
        h.y = to_tf32(v.y); l.y = to_tf32(v.y - h.y);
        h.z = to_tf32(v.z); l.z = to_tf32(v.z - h.z);
        h.w = to_tf32(v.w); l.w = to_tf32(v.w - h.w);
        H4[i] = h;
        L4[i] = l;
    }
}

// ---------------- tf32x2 GEMM (logits) ----------------
// C[M,N] = A[M,K] @ B[K,N] + bias[N]. A is pre-rounded tf32 (g_seq);
// Bh/Bl are pre-split — smem staging is pure float4 copies.
__global__ __launch_bounds__(256, 1)
void tf32_gemm_kernel(const float* __restrict__ A,
                      const float* __restrict__ Bhi, const float* __restrict__ Blo,
                      const float* __restrict__ bias, float* __restrict__ C,
                      int M, int N, int K)
{
    __shared__ float As[128][20];
    __shared__ float Bh[16][136];
    __shared__ float Bl[16][136];

    const int tid = threadIdx.x;
    const int lane = tid & 31;
    const int wid = tid >> 5;
    const int wr = wid >> 2;
    const int wc = wid & 3;
    const int bm = blockIdx.y * 128;
    const int bn = blockIdx.x * 128;

    float acc[4][4][4];
#pragma unroll
    for (int i = 0; i < 4; ++i)
#pragma unroll
        for (int j = 0; j < 4; ++j)
#pragma unroll
            for (int r = 0; r < 4; ++r) acc[i][j][r] = 0.f;

    float4 pa[2], pbh[2], pbl[2];
#pragma unroll
    for (int i = 0; i < 2; ++i) {
        int id = tid + i * 256;
        int m = id >> 2, kq = (id & 3) * 4;
        pa[i] = *(const float4*)(A + (size_t)(bm + m) * K + kq);
        int k = id >> 5, n4 = (id & 31) * 4;
        pbh[i] = *(const float4*)(Bhi + (size_t)k * N + bn + n4);
        pbl[i] = *(const float4*)(Blo + (size_t)k * N + bn + n4);
    }

    for (int kt = 0; kt < K; kt += 16) {
#pragma unroll
        for (int i = 0; i < 2; ++i) {
            int id = tid + i * 256;
            int m = id >> 2, kq = (id & 3) * 4;
            *(float4*)(&As[m][kq]) = pa[i];
            int k = id >> 5, n4 = (id & 31) * 4;
            *(float4*)(&Bh[k][n4]) = pbh[i];
            *(float4*)(&Bl[k][n4]) = pbl[i];
        }
        __syncthreads();

        if (kt + 16 < K) {
#pragma unroll
            for (int i = 0; i < 2; ++i) {
                int id = tid + i * 256;
                int m = id >> 2, kq = (id & 3) * 4;
                pa[i] = *(const float4*)(A + (size_t)(bm + m) * K + kt + 16 + kq);
                int k = id >> 5, n4 = (id & 31) * 4;
                pbh[i] = *(const float4*)(Bhi + (size_t)(kt + 16 + k) * N + bn + n4);
                pbl[i] = *(const float4*)(Blo + (size_t)(kt + 16 + k) * N + bn + n4);
            }
        }

#pragma unroll
        for (int ks = 0; ks < 16; ks += 8) {
            uint32_t af[4][4];
#pragma unroll
            for (int mt = 0; mt < 4; ++mt) {
                int r0 = wr * 64 + mt * 16 + (lane >> 2);
                int kc = ks + (lane & 3);
                af[mt][0] = __float_as_uint(As[r0][kc]);
                af[mt][1] = __float_as_uint(As[r0 + 8][kc]);
                af[mt][2] = __float_as_uint(As[r0][kc + 4]);
                af[mt][3] = __float_as_uint(As[r0 + 8][kc + 4]);
            }
#pragma unroll
            for (int nt = 0; nt < 4; ++nt) {
                int c0 = wc * 32 + nt * 8 + (lane >> 2);
                int kc = ks + (lane & 3);
                uint32_t bh0 = __float_as_uint(Bh[kc][c0]);
                uint32_t bh1 = __float_as_uint(Bh[kc + 4][c0]);
                uint32_t bl0 = __float_as_uint(Bl[kc][c0]);
                uint32_t bl1 = __float_as_uint(Bl[kc + 4][c0]);
#pragma unroll
                for (int mt = 0; mt < 4; ++mt) {
                    mma_tf32(acc[mt][nt], af[mt][0], af[mt][1], af[mt][2], af[mt][3], bh0, bh1);
                    mma_tf32(acc[mt][nt], af[mt][0], af[mt][1], af[mt][2], af[mt][3], bl0, bl1);
                }
            }
        }
        __syncthreads();
    }

#pragma unroll
    for (int mt = 0; mt < 4; ++mt) {
        int r0 = bm + wr * 64 + mt * 16 + (lane >> 2);
#pragma unroll
        for (int nt = 0; nt < 4; ++nt) {
            int col = bn + wc * 32 + nt * 8 + 2 * (lane & 3);
            float b0 = bias[col], b1 = bias[col + 1];
            float2 v0 = make_float2(acc[mt][nt][0] + b0, acc[mt][nt][1] + b1);
            float2 v1 = make_float2(acc[mt][nt][2] + b0, acc[mt][nt][3] + b1);
            *(float2*)(C + (size_t)r0 * N + col) = v0;
            *(float2*)(C + (size_t)(r0 + 8) * N + col) = v1;
        }
    }
}

// ---------------- fp32 SGEMM (xW, gathered) ----------------
template <bool GATHER>
__global__ __launch_bounds__(256, 2)
void sgemm_kernel(const float* __restrict__ A, const int* __restrict__ rowidx,
                  const float* __restrict__ B, const float* __restrict__ bias,
                  float* __restrict__ C, int M, int N, int K, int lda)
{
    constexpr int BM = 128, BN = 128, BK = 8, TM = 8, TN = 8;
    __shared__ float As[BK][BM];
    __shared__ float Bs[BK][BN];

    const int brow = blockIdx.y;
    const int bcol = blockIdx.x;
    const int tid = threadIdx.x;
    const int tx = tid % 16;
    const int ty = tid / 16;

    float acc[TM][TN];
#pragma unroll
    for (int i = 0; i < TM; ++i)
#pragma unroll
        for (int j = 0; j < TN; ++j) acc[i][j] = 0.f;

    const int a_r = tid >> 1;
    const int a_k = (tid & 1) * 4;
    const int b_k = tid >> 5;
    const int b_c = (tid & 31) * 4;

    const int grow = brow * BM + a_r;
    const float* Arow;
    if (GATHER) Arow = A + (size_t)rowidx[grow] * lda;
    else        Arow = A + (size_t)grow * lda;
    const float* Bbase = B + (size_t)bcol * BN;

    float4 av = *(const float4*)(Arow + a_k);
    float4 bv = *(const float4*)(Bbase + (size_t)b_k * N + b_c);

    for (int kt = 0; kt < K; kt += BK) {
        As[a_k + 0][a_r] = av.x;
        As[a_k + 1][a_r] = av.y;
        As[a_k + 2][a_r] = av.z;
        As[a_k + 3][a_r] = av.w;
        *(float4*)(&Bs[b_k][b_c]) = bv;
        __syncthreads();
        if (kt + BK < K) {
            av = *(const float4*)(Arow + kt + BK + a_k);
            bv = *(const float4*)(Bbase + (size_t)(kt + BK + b_k) * N + b_c);
        }
#pragma unroll
        for (int k = 0; k < BK; ++k) {
            float ra[TM], rb[TN];
#pragma unroll
            for (int i = 0; i < TM; ++i) ra[i] = As[k][ty * TM + i];
#pragma unroll
            for (int j = 0; j < TN; ++j) rb[j] = Bs[k][tx * TN + j];
#pragma unroll
            for (int i = 0; i < TM; ++i)
#pragma unroll
                for (int j = 0; j < TN; ++j)
                    acc[i][j] += ra[i] * rb[j];
        }
        __syncthreads();
    }

    const int ccol0 = bcol * BN + tx * TN;
#pragma unroll
    for (int i = 0; i < TM; ++i) {
        size_t r = (size_t)(brow * BM + ty * TM + i);
        float* crow = C + r * (size_t)N + ccol0;
#pragma unroll
        for (int j = 0; j < TN; j += 4) {
            float4 v;
            v.x = acc[i][j + 0] + bias[ccol0 + j + 0];
            v.y = acc[i][j + 1] + bias[ccol0 + j + 1];
            v.z = acc[i][j + 2] + bias[ccol0 + j + 2];
            v.w = acc[i][j + 3] + bias[ccol0 + j + 3];
            *(float4*)(crow + j) = v;
        }
    }
}

// ---------------- persistent LSTM scan ----------------
// One launch for all 64 steps. 128 blocks x 512 threads (1/SM, co-resident ->
// spin barrier safe). Block bx owns hcols [bx*8, bx*8+8) (32 z-cols); its U
// slice [1024][32] stays in smem for the whole scan.
// k split into NSL=8 cyclic sub-slices of 32 within each staged 256-k tile.
//
// Dynamic smem (floats): uS 1024*32 | hS 256*HPAD | zS NSL*32*ZPAD  (= 200 KB)
#define SCAN_SMEM_BYTES ((1024*32 + 256*HPAD + NSL*32*ZPAD) * 4)

__global__ __launch_bounds__(NTHR, 1)
void lstm_scan_kernel(const float* __restrict__ U)
{
    extern __shared__ float sm[];
    float* uS = sm;                    // [k][32]
    float* hS = sm + 1024 * 32;        // [k][HPAD]
    float* zS = hS + 256 * HPAD;       // [slice*32 + m][ZPAD]

    const int bx = blockIdx.x;         // 0..127
    const int tid = threadIdx.x;       // 0..511

    // ---- load U slice once: uS[k][c], c = g*8+j -> global col g*H + bx*8 + j
    for (int i = tid; i < 1024 * 8; i += NTHR) {
        int k = i >> 3;
        int c4 = (i & 7) * 4;
        int g = c4 >> 3;
        int j = c4 & 7;
        float4 v = *(const float4*)(U + (size_t)k * G4H + g * HH + bx * 8 + j);
        *(float4*)(uS + k * 32 + c4) = v;
    }

    // ---- cell state: owner threads tid < 256, thread owns (om, oj)
    const int om = (tid >> 3) & 31;    // batch row (valid when tid < 256)
    const int oj = tid & 7;            // local hcol
    const int ohcol = bx * 8 + oj;
    float creg = 0.f;
    if (tid < 256) creg = g_c[om * HH + ohcol];

    // ---- compute-phase indices: 8 sub-slices x 64 threads, 4m x 4c microtile
    const int ks = tid >> 6;           // 0..7 sub-slice
    const int tq = tid & 63;
    const int mg = tq >> 3;            // m base = mg*4
    const int cq = tq & 7;             // c base = cq*4

    for (int t = 0; t < TT; ++t) {
        const float* __restrict__ hprev = g_h[t & 1];

        float acc[4][4];               // [mi][ci]
#pragma unroll
        for (int i = 0; i < 4; ++i)
#pragma unroll
            for (int j = 0; j < 4; ++j) acc[i][j] = 0.f;

        for (int kt = 0; kt < HH; kt += 256) {
            __syncthreads();           // prior readers of hS done
            // stage h tile transposed: hS[k][m] = hprev[m][kt+k]
#pragma unroll
            for (int i = 0; i < 4; ++i) {
                int id = tid + i * NTHR;
                int m = id >> 6;               // 0..31
                int k4 = id & 63;              // float4 along k
                float4 v = *(const float4*)(hprev + m * HH + kt + k4 * 4);
                hS[(k4 * 4 + 0) * HPAD + m] = v.x;
                hS[(k4 * 4 + 1) * HPAD + m] = v.y;
                hS[(k4 * 4 + 2) * HPAD + m] = v.z;
                hS[(k4 * 4 + 3) * HPAD + m] = v.w;
            }
            __syncthreads();

            const float* hbase = hS + (ks * 32) * HPAD;
            const float* ubase = uS + (size_t)(kt + ks * 32) * 32;
#pragma unroll 8
            for (int k = 0; k < 32; ++k) {
                float4 hv = *(const float4*)(hbase + k * HPAD + mg * 4);
                float4 uv = *(const float4*)(ubase + k * 32 + cq * 4);
                float hvv[4] = {hv.x, hv.y, hv.z, hv.w};
                float uvv[4] = {uv.x, uv.y, uv.z, uv.w};
#pragma unroll
                for (int mi = 0; mi < 4; ++mi)
#pragma unroll
                    for (int ci = 0; ci < 4; ++ci)
                        acc[mi][ci] += hvv[mi] * uvv[ci];
            }
        }

        // ---- write slice partials
        __syncthreads();               // gate-phase of prev step done reading zS
#pragma unroll
        for (int mi = 0; mi < 4; ++mi) {
            float4 v = make_float4(acc[mi][0], acc[mi][1], acc[mi][2], acc[mi][3]);
            *(float4*)(zS + ((size_t)ks * 32 + mg * 4 + mi) * ZPAD + cq * 4) = v;
        }
        __syncthreads();

        // ---- gate fusion + state update for (om, ohcol)
        if (tid < 256) {
            float z[4];
#pragma unroll
            for (int g = 0; g < 4; ++g) {
                int c = g * 8 + oj;
                float s = 0.f;
#pragma unroll
                for (int sl = 0; sl < NSL; ++sl)
                    s += zS[((size_t)sl * 32 + om) * ZPAD + c];
                z[g] = s + g_xW[(size_t)(om * TT + t) * G4H + g * HH + ohcol];
            }
            float si = 1.f / (1.f + expf(-z[0]));
            float sf = 1.f / (1.f + expf(-z[1]));
            float tg = tanhf(z[2]);
            float so = 1.f / (1.f + expf(-z[3]));
            creg = sf * creg + si * tg;
            float hn = so * tanhf(creg);
            g_h[(t + 1) & 1][om * HH + ohcol] = hn;
            // pre-round for the tf32 logits GEMM (identical numerics to rounding there)
            g_seq[(size_t)(om * TT + t) * HH + ohcol] = to_tf32(hn);
        }

        // ---- grid barrier (release h writes, wait for all blocks)
        __threadfence();
        __syncthreads();
        if (tid == 0) {
            atomicAdd(&g_bar, 1);
            int target = NBLK * (t + 1);
            while (atomicAdd(&g_bar, 0) < target) { __nanosleep(20); }
        }
        __syncthreads();
        __threadfence();
    }

    // ---- write back cell state
    if (tid < 256) g_c[om * HH + ohcol] = creg;
}

// ---------------- launch ----------------
extern "C" void kernel_launch(void* const* d_in, const int* in_sizes, int n_in,
                              void* d_out, int out_size)
{
    const int*   x       = (const int*)d_in[0];
    const float* state_h = (const float*)d_in[1];
    const float* state_c = (const float*)d_in[2];
    const float* emb     = (const float*)d_in[3];
    const float* W       = (const float*)d_in[4];
    const float* U       = (const float*)d_in[5];
    const float* b       = (const float*)d_in[6];
    const float* dW      = (const float*)d_in[7];
    const float* db      = (const float*)d_in[8];
    float* out = (float*)d_out;

    float* xW_ptr  = nullptr;
    float* seq_ptr = nullptr;
    float* bh_ptr  = nullptr;
    float* bl_ptr  = nullptr;
    cudaGetSymbolAddress((void**)&xW_ptr,  g_xW);
    cudaGetSymbolAddress((void**)&seq_ptr, g_seq);
    cudaGetSymbolAddress((void**)&bh_ptr,  g_Bh);
    cudaGetSymbolAddress((void**)&bl_ptr,  g_Bl);

    // unconditional (no static guards); idempotent + capture-safe
    cudaFuncSetAttribute(lstm_scan_kernel,
                         cudaFuncAttributeMaxDynamicSharedMemorySize, SCAN_SMEM_BYTES);

    // 1) load initial state + reset barrier
    init_state_kernel<<<64, 512>>>(state_h, state_c);

    // 1b) pre-split dense_W into tf32 hi/lo (pure streaming)
    split_b_kernel<<<8192, 256>>>(dW);

    // 2) xW = emb_table[x] @ W + b   (M=2048, N=4096, K=512, gathered A, fp32)
    {
        dim3 grid(G4H / 128, NROWS / 128);
        sgemm_kernel<true><<<grid, 256>>>(emb, x, W, b, xW_ptr, NROWS, G4H, EE, EE);
    }

    // 3) LSTM scan: single persistent cooperative kernel (512 thr/block)
    lstm_scan_kernel<<<NBLK, NTHR, SCAN_SMEM_BYTES>>>(U);

    // 4) logits = seq @ dense_W + dense_b  (tf32x2 tensor cores, pre-split B)
    {
        dim3 grid(VV / 128, NROWS / 128);
        tf32_gemm_kernel<<<grid, 256>>>(seq_ptr, bh_ptr, bl_ptr, db, out, NROWS, VV, HH);
    }

    // 5) final h, c appended after logits
    float* out_h = out + (size_t)NROWS * VV;       // 65,536,000
    float* out_c = out_h + BB * HH;                // +32,768
    write_state_kernel<<<64, 512>>>(out_h, out_c);
}

// round 10
// speedup vs baseline: 1.8364x; 1.1715x over previous
#include <cuda_runtime.h>
#include <cuda_bf16.h>
#include <math.h>
#include <stdint.h>

// Problem constants
#define VV 32000
#define EE 512
#define HH 1024
#define BB 32
#define TT 64
#define G4H (4 * HH)          // 4096
#define NROWS (BB * TT)       // 2048

#define NBLK 128              // persistent blocks (each owns 8 hcols x 4 gates)
#define NTHR 512              // 16 warps

// smem word-layout constants (32-bit words)
#define UROW 516              // U row stride: [n][516] b32 words (1024 k -> 512 words + 4 pad)
#define HROW 260              // h chunk row stride: [m][260] (512 k -> 256 words + 4 pad)
#define ZROW 1154             // per-warp partial stride (32*36 + 2): bank-rotates across warps
#define ZFIN_OFF (2*32*UROW + 16*ZROW)          // zfinal offset in words
#define SCAN_SMEM_WORDS (ZFIN_OFF + 32*36)
#define SCAN_SMEM_BYTES (SCAN_SMEM_WORDS * 4)   // 210,560 B <= 227 KB

// ---------------- scratch (no allocs allowed) ----------------
__device__ float g_xW[NROWS * G4H];        // [b*T+t, 4H] input projections (+bias)
__device__ float g_seq[NROWS * HH];        // [b*T+t, H] hidden states (tf32-pre-rounded)
__device__ float g_h[2][BB * HH];          // ping-pong hidden state (full fp32)
__device__ float g_c[BB * HH];             // cell state
__device__ int   g_flag[NBLK];             // per-block step flags (reset by init kernel)
__device__ float g_Bh[(size_t)HH * VV];    // dense_W tf32 hi part
__device__ float g_Bl[(size_t)HH * VV];    // dense_W tf32 lo part

// ---------------- init / finalize ----------------
__global__ void init_state_kernel(const float* __restrict__ h0, const float* __restrict__ c0) {
    int i = blockIdx.x * blockDim.x + threadIdx.x;
    if (i < BB * HH) {
        g_h[0][i] = h0[i];
        g_c[i] = c0[i];
    }
    if (i < NBLK) g_flag[i] = 0;
}

__global__ void write_state_kernel(float* __restrict__ out_h, float* __restrict__ out_c) {
    int i = blockIdx.x * blockDim.x + threadIdx.x;
    if (i < BB * HH) {
        out_h[i] = g_h[0][i];   // after 64 steps (even), latest h is in buffer 0
        out_c[i] = g_c[i];
    }
}

// ---------------- tf32 helpers ----------------
__device__ __forceinline__ float to_tf32(float x) {
    uint32_t y;
    asm("cvt.rna.tf32.f32 %0, %1;" : "=r"(y) : "f"(x));
    return __uint_as_float(y);
}

__device__ __forceinline__ void mma_tf32(float* c, uint32_t a0, uint32_t a1, uint32_t a2, uint32_t a3,
                                         uint32_t b0, uint32_t b1) {
    asm volatile(
        "mma.sync.aligned.m16n8k8.row.col.f32.tf32.tf32.f32 "
        "{%0,%1,%2,%3}, {%4,%5,%6,%7}, {%8,%9}, {%0,%1,%2,%3};"
        : "+f"(c[0]), "+f"(c[1]), "+f"(c[2]), "+f"(c[3])
        : "r"(a0), "r"(a1), "r"(a2), "r"(a3), "r"(b0), "r"(b1));
}

// ---------------- bf16 helpers ----------------
__device__ __forceinline__ uint32_t packbf2(float a, float b) {  // a -> low half (first k)
    __nv_bfloat162 p = __floats2bfloat162_rn(a, b);
    return *reinterpret_cast<uint32_t*>(&p);
}
__device__ __forceinline__ float bfhi(float x) {
    return __bfloat162float(__float2bfloat16_rn(x));
}

__device__ __forceinline__ void mma_bf16(float* c, uint32_t a0, uint32_t a1, uint32_t a2, uint32_t a3,
                                         uint32_t b0, uint32_t b1) {
    asm volatile(
        "mma.sync.aligned.m16n8k16.row.col.f32.bf16.bf16.f32 "
        "{%0,%1,%2,%3}, {%4,%5,%6,%7}, {%8,%9}, {%0,%1,%2,%3};"
        : "+f"(c[0]), "+f"(c[1]), "+f"(c[2]), "+f"(c[3])
        : "r"(a0), "r"(a1), "r"(a2), "r"(a3), "r"(b0), "r"(b1));
}

// ---------------- B hi/lo pre-split (dense_W) ----------------
__global__ void split_b_kernel(const float* __restrict__ B) {
    const size_t n4 = (size_t)HH * VV / 4;
    size_t i = (size_t)blockIdx.x * blockDim.x + threadIdx.x;
    const size_t stride = (size_t)gridDim.x * blockDim.x;
    const float4* B4 = (const float4*)B;
    float4* H4 = (float4*)g_Bh;
    float4* L4 = (float4*)g_Bl;
    for (; i < n4; i += stride) {
        float4 v = B4[i];
        float4 h, l;
        h.x = to_tf32(v.x); l.x = to_tf32(v.x - h.x);
        h.y = to_tf32(v.y); l.y = to_tf32(v.y - h.y);
        h.z = to_tf32(v.z); l.z = to_tf32(v.z - h.z);
        h.w = to_tf32(v.w); l.w = to_tf32(v.w - h.w);
        H4[i] = h;
        L4[i] = l;
    }
}

// ---------------- tf32x2 GEMM (logits) ----------------
__global__ __launch_bounds__(256, 1)
void tf32_gemm_kernel(const float* __restrict__ A,
                      const float* __restrict__ Bhi, const float* __restrict__ Blo,
                      const float* __restrict__ bias, float* __restrict__ C,
                      int M, int N, int K)
{
    __shared__ float As[128][20];
    __shared__ float Bh[16][136];
    __shared__ float Bl[16][136];

    const int tid = threadIdx.x;
    const int lane = tid & 31;
    const int wid = tid >> 5;
    const int wr = wid >> 2;
    const int wc = wid & 3;
    const int bm = blockIdx.y * 128;
    const int bn = blockIdx.x * 128;

    float acc[4][4][4];
#pragma unroll
    for (int i = 0; i < 4; ++i)
#pragma unroll
        for (int j = 0; j < 4; ++j)
#pragma unroll
            for (int r = 0; r < 4; ++r) acc[i][j][r] = 0.f;

    float4 pa[2], pbh[2], pbl[2];
#pragma unroll
    for (int i = 0; i < 2; ++i) {
        int id = tid + i * 256;
        int m = id >> 2, kq = (id & 3) * 4;
        pa[i] = *(const float4*)(A + (size_t)(bm + m) * K + kq);
        int k = id >> 5, n4 = (id & 31) * 4;
        pbh[i] = *(const float4*)(Bhi + (size_t)k * N + bn + n4);
        pbl[i] = *(const float4*)(Blo + (size_t)k * N + bn + n4);
    }

    for (int kt = 0; kt < K; kt += 16) {
#pragma unroll
        for (int i = 0; i < 2; ++i) {
            int id = tid + i * 256;
            int m = id >> 2, kq = (id & 3) * 4;
            *(float4*)(&As[m][kq]) = pa[i];
            int k = id >> 5, n4 = (id & 31) * 4;
            *(float4*)(&Bh[k][n4]) = pbh[i];
            *(float4*)(&Bl[k][n4]) = pbl[i];
        }
        __syncthreads();

        if (kt + 16 < K) {
#pragma unroll
            for (int i = 0; i < 2; ++i) {
                int id = tid + i * 256;
                int m = id >> 2, kq = (id & 3) * 4;
                pa[i] = *(const float4*)(A + (size_t)(bm + m) * K + kt + 16 + kq);
                int k = id >> 5, n4 = (id & 31) * 4;
                pbh[i] = *(const float4*)(Bhi + (size_t)(kt + 16 + k) * N + bn + n4);
                pbl[i] = *(const float4*)(Blo + (size_t)(kt + 16 + k) * N + bn + n4);
            }
        }

#pragma unroll
        for (int ks = 0; ks < 16; ks += 8) {
            uint32_t af[4][4];
#pragma unroll
            for (int mt = 0; mt < 4; ++mt) {
                int r0 = wr * 64 + mt * 16 + (lane >> 2);
                int kc = ks + (lane & 3);
                af[mt][0] = __float_as_uint(As[r0][kc]);
                af[mt][1] = __float_as_uint(As[r0 + 8][kc]);
                af[mt][2] = __float_as_uint(As[r0][kc + 4]);
                af[mt][3] = __float_as_uint(As[r0 + 8][kc + 4]);
            }
#pragma unroll
            for (int nt = 0; nt < 4; ++nt) {
                int c0 = wc * 32 + nt * 8 + (lane >> 2);
                int kc = ks + (lane & 3);
                uint32_t bh0 = __float_as_uint(Bh[kc][c0]);
                uint32_t bh1 = __float_as_uint(Bh[kc + 4][c0]);
                uint32_t bl0 = __float_as_uint(Bl[kc][c0]);
                uint32_t bl1 = __float_as_uint(Bl[kc + 4][c0]);
#pragma unroll
                for (int mt = 0; mt < 4; ++mt) {
                    mma_tf32(acc[mt][nt], af[mt][0], af[mt][1], af[mt][2], af[mt][3], bh0, bh1);
                    mma_tf32(acc[mt][nt], af[mt][0], af[mt][1], af[mt][2], af[mt][3], bl0, bl1);
                }
            }
        }
        __syncthreads();
    }

#pragma unroll
    for (int mt = 0; mt < 4; ++mt) {
        int r0 = bm + wr * 64 + mt * 16 + (lane >> 2);
#pragma unroll
        for (int nt = 0; nt < 4; ++nt) {
            int col = bn + wc * 32 + nt * 8 + 2 * (lane & 3);
            float b0 = bias[col], b1 = bias[col + 1];
            float2 v0 = make_float2(acc[mt][nt][0] + b0, acc[mt][nt][1] + b1);
            float2 v1 = make_float2(acc[mt][nt][2] + b0, acc[mt][nt][3] + b1);
            *(float2*)(C + (size_t)r0 * N + col) = v0;
            *(float2*)(C + (size_t)(r0 + 8) * N + col) = v1;
        }
    }
}

// ---------------- fp32 SGEMM (xW, gathered) ----------------
template <bool GATHER>
__global__ __launch_bounds__(256, 2)
void sgemm_kernel(const float* __restrict__ A, const int* __restrict__ rowidx,
                  const float* __restrict__ B, const float* __restrict__ bias,
                  float* __restrict__ C, int M, int N, int K, int lda)
{
    constexpr int BM = 128, BN = 128, BK = 8, TM = 8, TN = 8;
    __shared__ float As[BK][BM];
    __shared__ float Bs[BK][BN];

    const int brow = blockIdx.y;
    const int bcol = blockIdx.x;
    const int tid = threadIdx.x;
    const int tx = tid % 16;
    const int ty = tid / 16;

    float acc[TM][TN];
#pragma unroll
    for (int i = 0; i < TM; ++i)
#pragma unroll
        for (int j = 0; j < TN; ++j) acc[i][j] = 0.f;

    const int a_r = tid >> 1;
    const int a_k = (tid & 1) * 4;
    const int b_k = tid >> 5;
    const int b_c = (tid & 31) * 4;

    const int grow = brow * BM + a_r;
    const float* Arow;
    if (GATHER) Arow = A + (size_t)rowidx[grow] * lda;
    else        Arow = A + (size_t)grow * lda;
    const float* Bbase = B + (size_t)bcol * BN;

    float4 av = *(const float4*)(Arow + a_k);
    float4 bv = *(const float4*)(Bbase + (size_t)b_k * N + b_c);

    for (int kt = 0; kt < K; kt += BK) {
        As[a_k + 0][a_r] = av.x;
        As[a_k + 1][a_r] = av.y;
        As[a_k + 2][a_r] = av.z;
        As[a_k + 3][a_r] = av.w;
        *(float4*)(&Bs[b_k][b_c]) = bv;
        __syncthreads();
        if (kt + BK < K) {
            av = *(const float4*)(Arow + kt + BK + a_k);
            bv = *(const float4*)(Bbase + (size_t)(kt + BK + b_k) * N + b_c);
        }
#pragma unroll
        for (int k = 0; k < BK; ++k) {
            float ra[TM], rb[TN];
#pragma unroll
            for (int i = 0; i < TM; ++i) ra[i] = As[k][ty * TM + i];
#pragma unroll
            for (int j = 0; j < TN; ++j) rb[j] = Bs[k][tx * TN + j];
#pragma unroll
            for (int i = 0; i < TM; ++i)
#pragma unroll
                for (int j = 0; j < TN; ++j)
                    acc[i][j] += ra[i] * rb[j];
        }
        __syncthreads();
    }

    const int ccol0 = bcol * BN + tx * TN;
#pragma unroll
    for (int i = 0; i < TM; ++i) {
        size_t r = (size_t)(brow * BM + ty * TM + i);
        float* crow = C + r * (size_t)N + ccol0;
#pragma unroll
        for (int j = 0; j < TN; j += 4) {
            float4 v;
            v.x = acc[i][j + 0] + bias[ccol0 + j + 0];
            v.y = acc[i][j + 1] + bias[ccol0 + j + 1];
            v.z = acc[i][j + 2] + bias[ccol0 + j + 2];
            v.w = acc[i][j + 3] + bias[ccol0 + j + 3];
            *(float4*)(crow + j) = v;
        }
    }
}

// ---------------- persistent LSTM scan (bf16x3 tensor cores) ----------------
// 128 blocks x 512 threads, 1/SM (co-resident -> flag barrier safe).
// Block bx owns 32 z-cols (8 hcols x 4 gates); z[32m x 32c] = h @ U-slice via
// mma.m16n8k16.bf16 with hi/lo splitting: z = hh*Uh + hl*Uh + hh*Ul.
// U converted once into smem [n][k] bf16 hi/lo. h staged per 512-k chunk as
// [m][k] bf16 hi/lo. 16-way k-partition across warps; smem reduction.
__global__ __launch_bounds__(NTHR, 1)
void lstm_scan_kernel(const float* __restrict__ U)
{
    extern __shared__ uint32_t smw[];
    uint32_t* uhi = smw;                       // [32 n][UROW]
    uint32_t* ulo = smw + 32 * UROW;
    uint32_t* hhi = smw + 2 * 32 * UROW;       // [32 m][HROW] (chunk)  -- unions with zS
    uint32_t* hlo = hhi + 32 * HROW;
    float*    zS  = (float*)(smw + 2 * 32 * UROW);   // [16 w][ZROW] partials (post-compute)
    float*    zfin = (float*)(smw + ZFIN_OFF);       // [32 m][36]

    const int bx = blockIdx.x;
    const int tid = threadIdx.x;
    const int w = tid >> 5;            // warp 0..15
    const int lane = tid & 31;
    const int g = lane >> 2;           // mma group row 0..7
    const int t4 = lane & 3;           // mma thread-in-group 0..3

    // ---- one-time: load U slice, convert to bf16 hi/lo, store [n][k] packed
    for (int i = tid; i < 4096; i += NTHR) {
        int kp = i >> 3;               // k pair index 0..511 (k = 2kp, 2kp+1)
        int c4 = (i & 7) * 4;          // local n base
        int gg = c4 >> 3;
        int jj = c4 & 7;
        int gcol = gg * HH + bx * 8 + jj;
        float4 v0 = *(const float4*)(U + (size_t)(2 * kp) * G4H + gcol);
        float4 v1 = *(const float4*)(U + (size_t)(2 * kp + 1) * G4H + gcol);
        const float a0[4] = {v0.x, v0.y, v0.z, v0.w};
        const float a1[4] = {v1.x, v1.y, v1.z, v1.w};
#pragma unroll
        for (int q = 0; q < 4; ++q) {
            float h0 = bfhi(a0[q]), l0 = a0[q] - h0;
            float h1 = bfhi(a1[q]), l1 = a1[q] - h1;
            uhi[(c4 + q) * UROW + kp] = packbf2(h0, h1);
            ulo[(c4 + q) * UROW + kp] = packbf2(l0, l1);
        }
    }
    __syncthreads();

    // ---- cell state: owner threads tid < 256, thread owns (om, oj)
    const int om = tid >> 3;           // batch row (valid when tid < 256)
    const int oj = tid & 7;            // local hcol
    const int ohcol = bx * 8 + oj;
    float creg = 0.f;
    if (tid < 256) creg = g_c[om * HH + ohcol];

    for (int t = 0; t < TT; ++t) {
        const float* __restrict__ hprev = g_h[t & 1];

        // prefetch xW for the gate phase (independent of h)
        float xw[4];
        if (tid < 256) {
            const float* xwp = g_xW + (size_t)(om * TT + t) * G4H + ohcol;
#pragma unroll
            for (int gg = 0; gg < 4; ++gg) xw[gg] = xwp[gg * HH];
        }

        float acc[2][4][4];
#pragma unroll
        for (int mt = 0; mt < 2; ++mt)
#pragma unroll
            for (int nt = 0; nt < 4; ++nt)
#pragma unroll
                for (int r = 0; r < 4; ++r) acc[mt][nt][r] = 0.f;

#pragma unroll
        for (int chunk = 0; chunk < 2; ++chunk) {
            __syncthreads();           // hS region free (prev phase done)
            // stage h chunk: fp32 -> bf16 hi/lo, [m][k] packed pairs
#pragma unroll
            for (int p = 0; p < 8; ++p) {
                int id = tid + p * NTHR;
                int m = id >> 7;               // 0..31
                int k4 = id & 127;             // float4 index within 512-k chunk
                float4 v = *(const float4*)(hprev + m * HH + chunk * 512 + k4 * 4);
                float hx = bfhi(v.x), hy = bfhi(v.y), hz = bfhi(v.z), hw = bfhi(v.w);
                uint2 whi = make_uint2(packbf2(hx, hy), packbf2(hz, hw));
                uint2 wlo = make_uint2(packbf2(v.x - hx, v.y - hy), packbf2(v.z - hz, v.w - hw));
                int word = m * HROW + k4 * 2;
                *(uint2*)(hhi + word) = whi;
                *(uint2*)(hlo + word) = wlo;
            }
            __syncthreads();

            // compute: warp w handles k16-steps {w, w+16} of this chunk
            const int ubase_k = chunk * 256;   // word offset into U rows
#pragma unroll
            for (int rep = 0; rep < 2; ++rep) {
                const int kw = (w + rep * 16) * 8;   // chunk-local word offset
                uint32_t ah[2][4], al[2][4], bh[4][2], bl[4][2];
#pragma unroll
                for (int mt = 0; mt < 2; ++mt) {
                    int base = (mt * 16 + g) * HROW + kw + t4;
                    ah[mt][0] = hhi[base];
                    ah[mt][1] = hhi[base + 8 * HROW];
                    ah[mt][2] = hhi[base + 4];
                    ah[mt][3] = hhi[base + 8 * HROW + 4];
                    al[mt][0] = hlo[base];
                    al[mt][1] = hlo[base + 8 * HROW];
                    al[mt][2] = hlo[base + 4];
                    al[mt][3] = hlo[base + 8 * HROW + 4];
                }
#pragma unroll
                for (int nt = 0; nt < 4; ++nt) {
                    int ub = (nt * 8 + g) * UROW + ubase_k + kw + t4;
                    bh[nt][0] = uhi[ub];
                    bh[nt][1] = uhi[ub + 4];
                    bl[nt][0] = ulo[ub];
                    bl[nt][1] = ulo[ub + 4];
                }
#pragma unroll
                for (int mt = 0; mt < 2; ++mt)
#pragma unroll
                    for (int nt = 0; nt < 4; ++nt) {
                        mma_bf16(acc[mt][nt], ah[mt][0], ah[mt][1], ah[mt][2], ah[mt][3], bh[nt][0], bh[nt][1]);
                        mma_bf16(acc[mt][nt], al[mt][0], al[mt][1], al[mt][2], al[mt][3], bh[nt][0], bh[nt][1]);
                        mma_bf16(acc[mt][nt], ah[mt][0], ah[mt][1], ah[mt][2], ah[mt][3], bl[nt][0], bl[nt][1]);
                    }
            }
        }
        __syncthreads();               // all frag reads done; zS may overwrite hS

        // ---- store per-warp 32x32 partials
#pragma unroll
        for (int mt = 0; mt < 2; ++mt)
#pragma unroll
            for (int nt = 0; nt < 4; ++nt) {
                int m = mt * 16 + g;
                int n = nt * 8 + t4 * 2;
                *(float2*)(zS + w * ZROW + m * 36 + n) = make_float2(acc[mt][nt][0], acc[mt][nt][1]);
                *(float2*)(zS + w * ZROW + (m + 8) * 36 + n) = make_float2(acc[mt][nt][2], acc[mt][nt][3]);
            }
        __syncthreads();

        // ---- reduce 16 partials -> zfinal
#pragma unroll
        for (int r = 0; r < 2; ++r) {
            int o = tid + r * NTHR;    // 0..1023
            int m = o >> 5, n = o & 31;
            float s = 0.f;
#pragma unroll
            for (int w2 = 0; w2 < 16; ++w2)
                s += zS[w2 * ZROW + m * 36 + n];
            zfin[m * 36 + n] = s;
        }
        __syncthreads();

        // ---- gate fusion + state update for (om, ohcol)
        if (tid < 256) {
            float z0 = zfin[om * 36 + 0 * 8 + oj] + xw[0];
            float z1 = zfin[om * 36 + 1 * 8 + oj] + xw[1];
            float z2 = zfin[om * 36 + 2 * 8 + oj] + xw[2];
            float z3 = zfin[om * 36 + 3 * 8 + oj] + xw[3];
            float si = 1.f / (1.f + expf(-z0));
            float sf = 1.f / (1.f + expf(-z1));
            float tg = tanhf(z2);
            float so = 1.f / (1.f + expf(-z3));
            creg = sf * creg + si * tg;
            float hn = so * tanhf(creg);
            g_h[(t + 1) & 1][om * HH + ohcol] = hn;
            g_seq[(size_t)(om * TT + t) * HH + ohcol] = to_tf32(hn);
        }

        // ---- grid barrier: per-block flags, parallel poll
        __threadfence();
        __syncthreads();
        if (tid == 0) ((volatile int*)g_flag)[bx] = t + 1;
        if (tid < NBLK) {
            while (((volatile int*)g_flag)[tid] < t + 1) { }
        }
        __syncthreads();
        __threadfence();
    }

    // ---- write back cell state
    if (tid < 256) g_c[om * HH + ohcol] = creg;
}

// ---------------- launch ----------------
extern "C" void kernel_launch(void* const* d_in, const int* in_sizes, int n_in,
                              void* d_out, int out_size)
{
    const int*   x       = (const int*)d_in[0];
    const float* state_h = (const float*)d_in[1];
    const float* state_c = (const float*)d_in[2];
    const float* emb     = (const float*)d_in[3];
    const float* W       = (const float*)d_in[4];
    const float* U       = (const float*)d_in[5];
    const float* b       = (const float*)d_in[6];
    const float* dW      = (const float*)d_in[7];
    const float* db      = (const float*)d_in[8];
    float* out = (float*)d_out;

    float* xW_ptr  = nullptr;
    float* seq_ptr = nullptr;
    float* bh_ptr  = nullptr;
    float* bl_ptr  = nullptr;
    cudaGetSymbolAddress((void**)&xW_ptr,  g_xW);
    cudaGetSymbolAddress((void**)&seq_ptr, g_seq);
    cudaGetSymbolAddress((void**)&bh_ptr,  g_Bh);
    cudaGetSymbolAddress((void**)&bl_ptr,  g_Bl);

    // unconditional (no static guards); idempotent + capture-safe
    cudaFuncSetAttribute(lstm_scan_kernel,
                         cudaFuncAttributeMaxDynamicSharedMemorySize, SCAN_SMEM_BYTES);

    // 1) load initial state + reset flags
    init_state_kernel<<<64, 512>>>(state_h, state_c);

    // 1b) pre-split dense_W into tf32 hi/lo (pure streaming)
    split_b_kernel<<<8192, 256>>>(dW);

    // 2) xW = emb_table[x] @ W + b   (M=2048, N=4096, K=512, gathered A, fp32)
    {
        dim3 grid(G4H / 128, NROWS / 128);
        sgemm_kernel<true><<<grid, 256>>>(emb, x, W, b, xW_ptr, NROWS, G4H, EE, EE);
    }

    // 3) LSTM scan: persistent cooperative kernel, bf16x3 tensor cores
    lstm_scan_kernel<<<NBLK, NTHR, SCAN_SMEM_BYTES>>>(U);

    // 4) logits = seq @ dense_W + dense_b  (tf32x2 tensor cores, pre-split B)
    {
        dim3 grid(VV / 128, NROWS / 128);
        tf32_gemm_kernel<<<grid, 256>>>(seq_ptr, bh_ptr, bl_ptr, db, out, NROWS, VV, HH);
    }

    // 5) final h, c appended after logits
    float* out_h = out + (size_t)NROWS * VV;       // 65,536,000
    float* out_c = out_h + BB * HH;                // +32,768
    write_state_kernel<<<64, 512>>>(out_h, out_c);
}